// round 1
// baseline (speedup 1.0000x reference)
#include <cuda_runtime.h>
#include <math.h>

#define BATCH    8
#define CH       128
#define T_AUDIO  16384
#define COND_CH  80
#define T_MEL    32
#define N_LAYERS 4
#define KPL      (CH*CH*3)        /* 49152 */
#define KC       (KPL*N_LAYERS)   /* 196608 */
#define BC       (CH*N_LAYERS)    /* 512 */

// ---------------- device scratch (no allocations allowed) ----------------
__device__ float g_hmean[BATCH*64];
__device__ float g_W[BATCH*N_LAYERS*KPL];          // [b][l][co][ci*3+k]
__device__ float g_bias[BATCH*N_LAYERS*CH];        // [b][l][co]
__device__ float g_buf0[(size_t)BATCH*CH*T_AUDIO]; // 64 MB
__device__ float g_buf1[(size_t)BATCH*CH*T_AUDIO]; // 64 MB

__device__ __forceinline__ float gelu_exact(float x) {
    return 0.5f * x * (1.0f + erff(x * 0.7071067811865475f));
}

// =========================================================================
// Kernel A: conditioning net. One block per batch sample.
// cond(80,32) -conv5,pad2-> gelu -> (64,32) -conv3,pad1-> gelu -> (64,32)
// then mean over T -> g_hmean[b][64]
// =========================================================================
__global__ void condnet_kernel(const float* __restrict__ cond,
                               const float* __restrict__ w0, const float* __restrict__ b0,
                               const float* __restrict__ w1, const float* __restrict__ b1) {
    extern __shared__ float smem[];
    float* sc  = smem;                      // 80*32
    float* sw0 = sc  + COND_CH*T_MEL;       // 64*80*5
    float* sw1 = sw0 + 64*COND_CH*5;        // 64*64*3
    float* sh0 = sw1 + 64*64*3;             // 64*32
    float* sh1 = sh0 + 64*T_MEL;            // 64*32

    const int b = blockIdx.x;
    const int tid = threadIdx.x;            // 256 threads

    for (int i = tid; i < COND_CH*T_MEL; i += 256) sc[i]  = cond[b*COND_CH*T_MEL + i];
    for (int i = tid; i < 64*COND_CH*5;  i += 256) sw0[i] = w0[i];
    for (int i = tid; i < 64*64*3;       i += 256) sw1[i] = w1[i];
    __syncthreads();

    const int og = tid >> 5;   // 0..7
    const int t  = tid & 31;   // 0..31

    float acc[8];
    #pragma unroll
    for (int r = 0; r < 8; ++r) acc[r] = b0[og*8 + r];
    for (int i = 0; i < COND_CH; ++i) {
        #pragma unroll
        for (int k = 0; k < 5; ++k) {
            int tt = t + k - 2;
            if (tt >= 0 && tt < T_MEL) {
                float xv = sc[i*T_MEL + tt];
                #pragma unroll
                for (int r = 0; r < 8; ++r)
                    acc[r] += sw0[((og*8 + r)*COND_CH + i)*5 + k] * xv;
            }
        }
    }
    #pragma unroll
    for (int r = 0; r < 8; ++r) sh0[(og*8 + r)*T_MEL + t] = gelu_exact(acc[r]);
    __syncthreads();

    #pragma unroll
    for (int r = 0; r < 8; ++r) acc[r] = b1[og*8 + r];
    for (int i = 0; i < 64; ++i) {
        #pragma unroll
        for (int k = 0; k < 3; ++k) {
            int tt = t + k - 1;
            if (tt >= 0 && tt < T_MEL) {
                float xv = sh0[i*T_MEL + tt];
                #pragma unroll
                for (int r = 0; r < 8; ++r)
                    acc[r] += sw1[((og*8 + r)*64 + i)*3 + k] * xv;
            }
        }
    }
    #pragma unroll
    for (int r = 0; r < 8; ++r) sh1[(og*8 + r)*T_MEL + t] = gelu_exact(acc[r]);
    __syncthreads();

    if (tid < 64) {
        float s = 0.0f;
        #pragma unroll
        for (int tt = 0; tt < T_MEL; ++tt) s += sh1[tid*T_MEL + tt];
        g_hmean[b*64 + tid] = s * (1.0f/T_MEL);
    }
}

// =========================================================================
// Kernel B: per-sample LVC weights. mean-over-T commuted through the 1x1
// conv: row c value per sample b = dot(w2[c,:], h_mean[b]) + b2[c].
// One thread per row c, 8 samples per thread. 770 blocks x 256.
// =========================================================================
__global__ void weights_kernel(const float* __restrict__ w2,
                               const float* __restrict__ b2) {
    __shared__ float sh[BATCH*64];
    const int tid = threadIdx.x;
    for (int i = tid; i < BATCH*64; i += 256) sh[i] = g_hmean[i];
    __syncthreads();

    const int c = blockIdx.x*256 + tid;   // < KC+BC = 197120 exactly
    float acc[BATCH];
    #pragma unroll
    for (int b = 0; b < BATCH; ++b) acc[b] = 0.0f;

    const float4* wr = (const float4*)(w2 + (size_t)c*64);
    #pragma unroll 4
    for (int j = 0; j < 16; ++j) {
        float4 w = wr[j];
        #pragma unroll
        for (int b = 0; b < BATCH; ++b) {
            const float* h = sh + b*64 + j*4;
            acc[b] += w.x*h[0] + w.y*h[1] + w.z*h[2] + w.w*h[3];
        }
    }
    const float bias = b2[c];
    if (c < KC) {
        const int l = c / KPL;
        const int r = c - l*KPL;          // co*384 + ci*3 + k
        #pragma unroll
        for (int b = 0; b < BATCH; ++b)
            g_W[(size_t)(b*N_LAYERS + l)*KPL + r] = acc[b] + bias;
    } else {
        const int idx = c - KC;           // l*128 + co
        #pragma unroll
        for (int b = 0; b < BATCH; ++b)
            g_bias[b*N_LAYERS*CH + idx] = acc[b] + bias;
    }
}

// =========================================================================
// Conv layer kernel. Block = (co-tile 64) x (t-chunk 512 = 4 tiles of 128).
// Grid (32, 2, 8). smem: W[k][ci][co] (96KB) + x[128][144] (72KB) + bias.
// Inner loop uses packed fma.rn.f32x2 (co-pairs in lanes) -> 2 FMA/instr.
// =========================================================================
#define FFMA2(a_, w_, x_) asm("fma.rn.f32x2 %0, %1, %2, %0;" : "+l"(a_) : "l"(w_), "l"(x_))
#define CONV_SMEM_FLOATS (3*CH*64 + CH*144 + 64)

template<int DIL, bool FINAL>
__global__ void __launch_bounds__(256, 1)
lvc_conv(const float* __restrict__ xin, float* __restrict__ xout,
         int layer, const float* __restrict__ alpha) {
    extern __shared__ float smem[];
    float* sW = smem;                 // [3][128][64]
    float* sX = smem + 3*CH*64;       // [128][144]
    float* sB = sX + CH*144;          // [64]

    const int b   = blockIdx.z;
    const int co0 = blockIdx.y * 64;
    const int tid = threadIdx.x;
    const int cg  = tid >> 5;         // 0..7
    const int tg  = tid & 31;         // 0..31

    // stage weights, transposed to [k][ci][co] (gmem read coalesced)
    const float* Wg = g_W + (size_t)(b*N_LAYERS + layer)*KPL + (size_t)co0*384;
    for (int idx = tid; idx < 64*384; idx += 256) {
        int co = idx / 384;
        int r  = idx - co*384;
        int ci = r / 3;
        int k  = r - ci*3;
        sW[(k*CH + ci)*64 + co] = Wg[idx];
    }
    if (tid < 64) sB[tid] = g_bias[(b*N_LAYERS + layer)*CH + co0 + tid];

    const float* xb = xin  + (size_t)b*CH*T_AUDIO;
    float*       yb = xout + (size_t)b*CH*T_AUDIO;
    const int width = 128 + 2*DIL;

    for (int tile = 0; tile < 4; ++tile) {
        const int t0 = blockIdx.x*512 + tile*128;
        __syncthreads();   // sW/sB ready; sX from previous tile fully consumed
        for (int idx = tid; idx < CH*width; idx += 256) {
            int ci  = idx / width;
            int col = idx - ci*width;
            int t   = t0 - DIL + col;
            sX[ci*144 + col] = (t >= 0 && t < T_AUDIO) ? xb[(size_t)ci*T_AUDIO + t] : 0.0f;
        }
        __syncthreads();

        unsigned long long acc[4][4];
        #pragma unroll
        for (int p = 0; p < 4; ++p)
            #pragma unroll
            for (int j = 0; j < 4; ++j) acc[p][j] = 0ULL;

        const float* xbase = sX + tg;
        const float* wbase = sW + cg*8;
        #pragma unroll 1
        for (int ci = 0; ci < CH; ++ci) {
            const float* xr = xbase + ci*144;
            #pragma unroll
            for (int k = 0; k < 3; ++k) {
                const int off = k*DIL;
                float x0 = xr[off +  0];
                float x1 = xr[off + 32];
                float x2 = xr[off + 64];
                float x3 = xr[off + 96];
                unsigned long long xp0, xp1, xp2, xp3;
                asm("mov.b64 %0, {%1, %1};" : "=l"(xp0) : "f"(x0));
                asm("mov.b64 %0, {%1, %1};" : "=l"(xp1) : "f"(x1));
                asm("mov.b64 %0, {%1, %1};" : "=l"(xp2) : "f"(x2));
                asm("mov.b64 %0, {%1, %1};" : "=l"(xp3) : "f"(x3));
                const unsigned long long* wq =
                    (const unsigned long long*)(wbase + (k*CH + ci)*64);
                unsigned long long wa = wq[0], wb = wq[1], wc = wq[2], wd = wq[3];
                FFMA2(acc[0][0], wa, xp0); FFMA2(acc[0][1], wa, xp1);
                FFMA2(acc[0][2], wa, xp2); FFMA2(acc[0][3], wa, xp3);
                FFMA2(acc[1][0], wb, xp0); FFMA2(acc[1][1], wb, xp1);
                FFMA2(acc[1][2], wb, xp2); FFMA2(acc[1][3], wb, xp3);
                FFMA2(acc[2][0], wc, xp0); FFMA2(acc[2][1], wc, xp1);
                FFMA2(acc[2][2], wc, xp2); FFMA2(acc[2][3], wc, xp3);
                FFMA2(acc[3][0], wd, xp0); FFMA2(acc[3][1], wd, xp1);
                FFMA2(acc[3][2], wd, xp2); FFMA2(acc[3][3], wd, xp3);
            }
        }

        #pragma unroll
        for (int p = 0; p < 4; ++p) {
            #pragma unroll
            for (int lane = 0; lane < 2; ++lane) {
                const int col = cg*8 + 2*p + lane;   // local co
                const int cog = co0 + col;           // global co
                const float bias = sB[col];
                float a = 0.0f, inva = 0.0f;
                if (FINAL) { a = alpha[cog]; inva = 1.0f/(a + 1e-8f); }
                #pragma unroll
                for (int j = 0; j < 4; ++j) {
                    unsigned int u = lane ? (unsigned int)(acc[p][j] >> 32)
                                          : (unsigned int)(acc[p][j] & 0xFFFFFFFFULL);
                    float v = __uint_as_float(u);
                    const int tl = tg + 32*j;
                    float y = v + bias + sX[cog*144 + DIL + tl];  // residual from smem
                    if (FINAL) {
                        float s = sinf(a*y);
                        y = y + inva*s*s;
                    }
                    yb[(size_t)cog*T_AUDIO + t0 + tl] = y;
                }
            }
        }
    }
}

// =========================================================================
extern "C" void kernel_launch(void* const* d_in, const int* in_sizes, int n_in,
                              void* d_out, int out_size) {
    const float* x     = (const float*)d_in[0];
    const float* cond  = (const float*)d_in[1];
    const float* w0    = (const float*)d_in[2];
    const float* b0    = (const float*)d_in[3];
    const float* w1    = (const float*)d_in[4];
    const float* b1    = (const float*)d_in[5];
    const float* w2    = (const float*)d_in[6];
    const float* b2    = (const float*)d_in[7];
    const float* alpha = (const float*)d_in[8];
    float* out = (float*)d_out;

    float *buf0, *buf1;
    cudaGetSymbolAddress((void**)&buf0, g_buf0);
    cudaGetSymbolAddress((void**)&buf1, g_buf1);

    const int smemA = (COND_CH*T_MEL + 64*COND_CH*5 + 64*64*3 + 64*T_MEL + 64*T_MEL)
                      * (int)sizeof(float);
    cudaFuncSetAttribute(condnet_kernel, cudaFuncAttributeMaxDynamicSharedMemorySize, smemA);
    condnet_kernel<<<BATCH, 256, smemA>>>(cond, w0, b0, w1, b1);

    weights_kernel<<<(KC + BC)/256, 256>>>(w2, b2);

    const int smemC = CONV_SMEM_FLOATS * (int)sizeof(float);
    cudaFuncSetAttribute(lvc_conv<1,false>, cudaFuncAttributeMaxDynamicSharedMemorySize, smemC);
    cudaFuncSetAttribute(lvc_conv<2,false>, cudaFuncAttributeMaxDynamicSharedMemorySize, smemC);
    cudaFuncSetAttribute(lvc_conv<4,false>, cudaFuncAttributeMaxDynamicSharedMemorySize, smemC);
    cudaFuncSetAttribute(lvc_conv<8,true >, cudaFuncAttributeMaxDynamicSharedMemorySize, smemC);

    dim3 grid(32, 2, BATCH);
    lvc_conv<1,false><<<grid, 256, smemC>>>(x,    buf0, 0, nullptr);
    lvc_conv<2,false><<<grid, 256, smemC>>>(buf0, buf1, 1, nullptr);
    lvc_conv<4,false><<<grid, 256, smemC>>>(buf1, buf0, 2, nullptr);
    lvc_conv<8,true ><<<grid, 256, smemC>>>(buf0, out,  3, alpha);
}

// round 2
// speedup vs baseline: 1.1469x; 1.1469x over previous
#include <cuda_runtime.h>
#include <math.h>

#define BATCH    8
#define CH       128
#define T_AUDIO  16384
#define COND_CH  80
#define T_MEL    32
#define N_LAYERS 4
#define KPL      (CH*CH*3)        /* 49152 */
#define KC       (KPL*N_LAYERS)   /* 196608 */
#define BC       (CH*N_LAYERS)    /* 512 */

// ---------------- device scratch (no allocations allowed) ----------------
__device__ float g_hmean[BATCH*64];
__device__ float g_W[BATCH*N_LAYERS*KPL];          // [b][l][co][ci*3+k]
__device__ float g_bias[BATCH*N_LAYERS*CH];        // [b][l][co]
__device__ float g_buf0[(size_t)BATCH*CH*T_AUDIO]; // 64 MB
__device__ float g_buf1[(size_t)BATCH*CH*T_AUDIO]; // 64 MB

__device__ __forceinline__ float gelu_exact(float x) {
    return 0.5f * x * (1.0f + erff(x * 0.7071067811865475f));
}

// =========================================================================
// Kernel A: conditioning net. One block per batch sample.
// =========================================================================
__global__ void condnet_kernel(const float* __restrict__ cond,
                               const float* __restrict__ w0, const float* __restrict__ b0,
                               const float* __restrict__ w1, const float* __restrict__ b1) {
    extern __shared__ float smem[];
    float* sc  = smem;                      // 80*32
    float* sw0 = sc  + COND_CH*T_MEL;       // 64*80*5
    float* sw1 = sw0 + 64*COND_CH*5;        // 64*64*3
    float* sh0 = sw1 + 64*64*3;             // 64*32
    float* sh1 = sh0 + 64*T_MEL;            // 64*32

    const int b = blockIdx.x;
    const int tid = threadIdx.x;            // 256 threads

    for (int i = tid; i < COND_CH*T_MEL; i += 256) sc[i]  = cond[b*COND_CH*T_MEL + i];
    for (int i = tid; i < 64*COND_CH*5;  i += 256) sw0[i] = w0[i];
    for (int i = tid; i < 64*64*3;       i += 256) sw1[i] = w1[i];
    __syncthreads();

    const int og = tid >> 5;   // 0..7
    const int t  = tid & 31;   // 0..31

    float acc[8];
    #pragma unroll
    for (int r = 0; r < 8; ++r) acc[r] = b0[og*8 + r];
    for (int i = 0; i < COND_CH; ++i) {
        #pragma unroll
        for (int k = 0; k < 5; ++k) {
            int tt = t + k - 2;
            if (tt >= 0 && tt < T_MEL) {
                float xv = sc[i*T_MEL + tt];
                #pragma unroll
                for (int r = 0; r < 8; ++r)
                    acc[r] += sw0[((og*8 + r)*COND_CH + i)*5 + k] * xv;
            }
        }
    }
    #pragma unroll
    for (int r = 0; r < 8; ++r) sh0[(og*8 + r)*T_MEL + t] = gelu_exact(acc[r]);
    __syncthreads();

    #pragma unroll
    for (int r = 0; r < 8; ++r) acc[r] = b1[og*8 + r];
    for (int i = 0; i < 64; ++i) {
        #pragma unroll
        for (int k = 0; k < 3; ++k) {
            int tt = t + k - 1;
            if (tt >= 0 && tt < T_MEL) {
                float xv = sh0[i*T_MEL + tt];
                #pragma unroll
                for (int r = 0; r < 8; ++r)
                    acc[r] += sw1[((og*8 + r)*64 + i)*3 + k] * xv;
            }
        }
    }
    #pragma unroll
    for (int r = 0; r < 8; ++r) sh1[(og*8 + r)*T_MEL + t] = gelu_exact(acc[r]);
    __syncthreads();

    if (tid < 64) {
        float s = 0.0f;
        #pragma unroll
        for (int tt = 0; tt < T_MEL; ++tt) s += sh1[tid*T_MEL + tt];
        g_hmean[b*64 + tid] = s * (1.0f/T_MEL);
    }
}

// =========================================================================
// Kernel B: per-sample LVC weights (mean commuted through the 1x1 conv).
// =========================================================================
__global__ void weights_kernel(const float* __restrict__ w2,
                               const float* __restrict__ b2) {
    __shared__ float sh[BATCH*64];
    const int tid = threadIdx.x;
    for (int i = tid; i < BATCH*64; i += 256) sh[i] = g_hmean[i];
    __syncthreads();

    const int c = blockIdx.x*256 + tid;   // < KC+BC = 197120 exactly
    float acc[BATCH];
    #pragma unroll
    for (int b = 0; b < BATCH; ++b) acc[b] = 0.0f;

    const float4* wr = (const float4*)(w2 + (size_t)c*64);
    #pragma unroll 4
    for (int j = 0; j < 16; ++j) {
        float4 w = wr[j];
        #pragma unroll
        for (int b = 0; b < BATCH; ++b) {
            const float* h = sh + b*64 + j*4;
            acc[b] += w.x*h[0] + w.y*h[1] + w.z*h[2] + w.w*h[3];
        }
    }
    const float bias = b2[c];
    if (c < KC) {
        const int l = c / KPL;
        const int r = c - l*KPL;          // co*384 + ci*3 + k
        #pragma unroll
        for (int b = 0; b < BATCH; ++b)
            g_W[(size_t)(b*N_LAYERS + l)*KPL + r] = acc[b] + bias;
    } else {
        const int idx = c - KC;           // l*128 + co
        #pragma unroll
        for (int b = 0; b < BATCH; ++b)
            g_bias[b*N_LAYERS*CH + idx] = acc[b] + bias;
    }
}

// =========================================================================
// Conv layer kernel. Block = 64 co x 512 t (4 tiles of 128), 512 threads.
// 16 warps: warp (w&7) -> co group of 8, (w>>3) -> t half of 64.
// Weights staged [k][ci][co] -> 2x LDS.128 broadcast per (ci,k).
// Packed fma.rn.f32x2, co-pairs in lanes.
// =========================================================================
#define FFMA2(a_, w_, x_) asm("fma.rn.f32x2 %0, %1, %2, %0;" : "+l"(a_) : "l"(w_), "l"(x_))
#define CONV_SMEM_FLOATS (3*CH*64 + CH*144 + 64)

template<int DIL, bool FINAL>
__global__ void __launch_bounds__(512, 1)
lvc_conv(const float* __restrict__ xin, float* __restrict__ xout,
         int layer, const float* __restrict__ alpha) {
    extern __shared__ float smem[];
    float* sW = smem;                 // [3][128][64]
    float* sX = smem + 3*CH*64;       // [128][144]
    float* sB = sX + CH*144;          // [64]

    const int b   = blockIdx.z;
    const int co0 = blockIdx.y * 64;
    const int tid = threadIdx.x;
    const int w   = tid >> 5;         // 0..15
    const int tg  = tid & 31;         // lane
    const int cg  = w & 7;            // co group (8 co each)
    const int th  = w >> 3;           // t half (64 each)

    // stage weights, transposed to [k][ci][co] (gmem read coalesced)
    const float* Wg = g_W + (size_t)(b*N_LAYERS + layer)*KPL + (size_t)co0*384;
    for (int idx = tid; idx < 64*384; idx += 512) {
        int co = idx / 384;
        int r  = idx - co*384;
        int ci = r / 3;
        int k  = r - ci*3;
        sW[(k*CH + ci)*64 + co] = Wg[idx];
    }
    if (tid < 64) sB[tid] = g_bias[(b*N_LAYERS + layer)*CH + co0 + tid];

    const float* xb = xin  + (size_t)b*CH*T_AUDIO;
    float*       yb = xout + (size_t)b*CH*T_AUDIO;
    const int width = 128 + 2*DIL;

    for (int tile = 0; tile < 4; ++tile) {
        const int t0 = blockIdx.x*512 + tile*128;
        __syncthreads();   // sW/sB ready; sX from previous tile fully consumed
        for (int idx = tid; idx < CH*width; idx += 512) {
            int ci  = idx / width;
            int col = idx - ci*width;
            int t   = t0 - DIL + col;
            sX[ci*144 + col] = (t >= 0 && t < T_AUDIO) ? xb[(size_t)ci*T_AUDIO + t] : 0.0f;
        }
        __syncthreads();

        unsigned long long acc[4][2];
        #pragma unroll
        for (int p = 0; p < 4; ++p) { acc[p][0] = 0ULL; acc[p][1] = 0ULL; }

        const float* xbase = sX + th*64 + tg;
        const float* wbase = sW + cg*8;
        #pragma unroll 2
        for (int ci = 0; ci < CH; ++ci) {
            const float* xr = xbase + ci*144;
            #pragma unroll
            for (int k = 0; k < 3; ++k) {
                const int off = k*DIL;
                float x0 = xr[off +  0];
                float x1 = xr[off + 32];
                unsigned long long xp0, xp1;
                asm("mov.b64 %0, {%1, %1};" : "=l"(xp0) : "f"(x0));
                asm("mov.b64 %0, {%1, %1};" : "=l"(xp1) : "f"(x1));
                const ulonglong2* wq = (const ulonglong2*)(wbase + (k*CH + ci)*64);
                ulonglong2 wA = wq[0];   // co pairs 0,1
                ulonglong2 wB = wq[1];   // co pairs 2,3
                FFMA2(acc[0][0], wA.x, xp0); FFMA2(acc[0][1], wA.x, xp1);
                FFMA2(acc[1][0], wA.y, xp0); FFMA2(acc[1][1], wA.y, xp1);
                FFMA2(acc[2][0], wB.x, xp0); FFMA2(acc[2][1], wB.x, xp1);
                FFMA2(acc[3][0], wB.y, xp0); FFMA2(acc[3][1], wB.y, xp1);
            }
        }

        #pragma unroll
        for (int p = 0; p < 4; ++p) {
            #pragma unroll
            for (int lane = 0; lane < 2; ++lane) {
                const int col = cg*8 + 2*p + lane;   // local co
                const int cog = co0 + col;           // global co
                const float bias = sB[col];
                float a = 0.0f, inva = 0.0f;
                if (FINAL) { a = alpha[cog]; inva = 1.0f/(a + 1e-8f); }
                #pragma unroll
                for (int j = 0; j < 2; ++j) {
                    unsigned int u = lane ? (unsigned int)(acc[p][j] >> 32)
                                          : (unsigned int)(acc[p][j] & 0xFFFFFFFFULL);
                    float v = __uint_as_float(u);
                    const int tl = th*64 + tg + 32*j;
                    float y = v + bias + sX[cog*144 + DIL + tl];  // residual from smem
                    if (FINAL) {
                        float s = sinf(a*y);
                        y = y + inva*s*s;
                    }
                    yb[(size_t)cog*T_AUDIO + t0 + tl] = y;
                }
            }
        }
    }
}

// =========================================================================
extern "C" void kernel_launch(void* const* d_in, const int* in_sizes, int n_in,
                              void* d_out, int out_size) {
    const float* x     = (const float*)d_in[0];
    const float* cond  = (const float*)d_in[1];
    const float* w0    = (const float*)d_in[2];
    const float* b0    = (const float*)d_in[3];
    const float* w1    = (const float*)d_in[4];
    const float* b1    = (const float*)d_in[5];
    const float* w2    = (const float*)d_in[6];
    const float* b2    = (const float*)d_in[7];
    const float* alpha = (const float*)d_in[8];
    float* out = (float*)d_out;

    float *buf0, *buf1;
    cudaGetSymbolAddress((void**)&buf0, g_buf0);
    cudaGetSymbolAddress((void**)&buf1, g_buf1);

    const int smemA = (COND_CH*T_MEL + 64*COND_CH*5 + 64*64*3 + 64*T_MEL + 64*T_MEL)
                      * (int)sizeof(float);
    cudaFuncSetAttribute(condnet_kernel, cudaFuncAttributeMaxDynamicSharedMemorySize, smemA);
    condnet_kernel<<<BATCH, 256, smemA>>>(cond, w0, b0, w1, b1);

    weights_kernel<<<(KC + BC)/256, 256>>>(w2, b2);

    const int smemC = CONV_SMEM_FLOATS * (int)sizeof(float);
    cudaFuncSetAttribute(lvc_conv<1,false>, cudaFuncAttributeMaxDynamicSharedMemorySize, smemC);
    cudaFuncSetAttribute(lvc_conv<2,false>, cudaFuncAttributeMaxDynamicSharedMemorySize, smemC);
    cudaFuncSetAttribute(lvc_conv<4,false>, cudaFuncAttributeMaxDynamicSharedMemorySize, smemC);
    cudaFuncSetAttribute(lvc_conv<8,true >, cudaFuncAttributeMaxDynamicSharedMemorySize, smemC);

    dim3 grid(32, 2, BATCH);
    lvc_conv<1,false><<<grid, 512, smemC>>>(x,    buf0, 0, nullptr);
    lvc_conv<2,false><<<grid, 512, smemC>>>(buf0, buf1, 1, nullptr);
    lvc_conv<4,false><<<grid, 512, smemC>>>(buf1, buf0, 2, nullptr);
    lvc_conv<8,true ><<<grid, 512, smemC>>>(buf0, out,  3, alpha);
}

// round 4
// speedup vs baseline: 1.9826x; 1.7287x over previous
#include <cuda_runtime.h>
#include <math.h>
#include <stdint.h>

#define BATCH    8
#define CH       128
#define T_AUDIO  16384
#define COND_CH  80
#define T_MEL    32
#define N_LAYERS 4
#define KPL      (CH*CH*3)        /* 49152 */
#define KC       (KPL*N_LAYERS)   /* 196608 */
#define BC       (CH*N_LAYERS)    /* 512 */

#define KTOT     384
#define NSTEP    48               /* 384/8 k-steps */
#define NT       128              /* t-tile */
#define TILES    (T_AUDIO/NT)     /* 128 */
#define CTAS_X   9                /* persistent groups per (b,half) */
#define WHALF    24576            /* 64co x 384k floats per (b,l,half) */
#define XSTRIDE  152              /* x tile row stride: 152%32=24 -> B frags conflict-free */

// ---------------- device scratch ----------------
__device__ float g_hmean[BATCH*64];
__device__ float g_W[BATCH*N_LAYERS*2*WHALF];      // fragment-major per (b,l,half)
__device__ float g_bias[BATCH*N_LAYERS*CH];
__device__ float g_buf0[(size_t)BATCH*CH*T_AUDIO];
__device__ float g_buf1[(size_t)BATCH*CH*T_AUDIO];

__device__ __forceinline__ float gelu_exact(float x) {
    return 0.5f * x * (1.0f + erff(x * 0.7071067811865475f));
}
__device__ __forceinline__ uint32_t to_tf32(float f) {
    uint32_t u;
    asm("cvt.rna.tf32.f32 %0, %1;" : "=r"(u) : "f"(f));
    return u;
}

#define MMA8(d_, a_, b_) \
  asm volatile("mma.sync.aligned.m16n8k8.row.col.f32.tf32.tf32.f32 " \
    "{%0,%1,%2,%3}, {%4,%5,%6,%7}, {%8,%9}, {%0,%1,%2,%3};" \
    : "+f"((d_)[0]), "+f"((d_)[1]), "+f"((d_)[2]), "+f"((d_)[3]) \
    : "r"((a_)[0]), "r"((a_)[1]), "r"((a_)[2]), "r"((a_)[3]), \
      "r"((b_)[0]), "r"((b_)[1]))

// =========================================================================
// Kernel A: conditioning net (unchanged)
// =========================================================================
__global__ void condnet_kernel(const float* __restrict__ cond,
                               const float* __restrict__ w0, const float* __restrict__ b0,
                               const float* __restrict__ w1, const float* __restrict__ b1) {
    extern __shared__ float smemf[];
    float* sc  = smemf;
    float* sw0 = sc  + COND_CH*T_MEL;
    float* sw1 = sw0 + 64*COND_CH*5;
    float* sh0 = sw1 + 64*64*3;
    float* sh1 = sh0 + 64*T_MEL;

    const int b = blockIdx.x;
    const int tid = threadIdx.x;

    for (int i = tid; i < COND_CH*T_MEL; i += 256) sc[i]  = cond[b*COND_CH*T_MEL + i];
    for (int i = tid; i < 64*COND_CH*5;  i += 256) sw0[i] = w0[i];
    for (int i = tid; i < 64*64*3;       i += 256) sw1[i] = w1[i];
    __syncthreads();

    const int og = tid >> 5;
    const int t  = tid & 31;

    float acc[8];
    #pragma unroll
    for (int r = 0; r < 8; ++r) acc[r] = b0[og*8 + r];
    for (int i = 0; i < COND_CH; ++i) {
        #pragma unroll
        for (int k = 0; k < 5; ++k) {
            int tt = t + k - 2;
            if (tt >= 0 && tt < T_MEL) {
                float xv = sc[i*T_MEL + tt];
                #pragma unroll
                for (int r = 0; r < 8; ++r)
                    acc[r] += sw0[((og*8 + r)*COND_CH + i)*5 + k] * xv;
            }
        }
    }
    #pragma unroll
    for (int r = 0; r < 8; ++r) sh0[(og*8 + r)*T_MEL + t] = gelu_exact(acc[r]);
    __syncthreads();

    #pragma unroll
    for (int r = 0; r < 8; ++r) acc[r] = b1[og*8 + r];
    for (int i = 0; i < 64; ++i) {
        #pragma unroll
        for (int k = 0; k < 3; ++k) {
            int tt = t + k - 1;
            if (tt >= 0 && tt < T_MEL) {
                float xv = sh0[i*T_MEL + tt];
                #pragma unroll
                for (int r = 0; r < 8; ++r)
                    acc[r] += sw1[((og*8 + r)*64 + i)*3 + k] * xv;
            }
        }
    }
    #pragma unroll
    for (int r = 0; r < 8; ++r) sh1[(og*8 + r)*T_MEL + t] = gelu_exact(acc[r]);
    __syncthreads();

    if (tid < 64) {
        float s = 0.0f;
        #pragma unroll
        for (int tt = 0; tt < T_MEL; ++tt) s += sh1[tid*T_MEL + tt];
        g_hmean[b*64 + tid] = s * (1.0f/T_MEL);
    }
}

// =========================================================================
// Kernel B: LVC weights. Output directly in mma-fragment-major order,
// tf32-pre-rounded. gidx in [0,KC) enumerates (l, half, e) with
// e = ((ks*4 + mt)*32 + lane)*4 + j  (A-fragment layout of m16n8k8).
// =========================================================================
__global__ void weights_kernel(const float* __restrict__ w2,
                               const float* __restrict__ b2) {
    __shared__ float sh[BATCH*64];
    const int tid = threadIdx.x;
    for (int i = tid; i < BATCH*64; i += 256) sh[i] = g_hmean[i];
    __syncthreads();

    const int gidx = blockIdx.x*256 + tid;    // < 197120
    size_t c_row;
    int l = 0, half = 0, e = 0;
    const bool isK = gidx < KC;
    if (isK) {
        l = gidx / (2*WHALF);
        int rem = gidx - l*(2*WHALF);
        half = rem / WHALF;
        e = rem - half*WHALF;
        const int j    = e & 3;
        const int lane = (e >> 2) & 31;
        const int mt   = (e >> 7) & 3;
        const int ks   = e >> 9;
        const int co_l = mt*16 + (lane >> 2) + (j & 1)*8;
        const int kcol = (lane & 3) + ((j >> 1) & 1)*4;
        const int kidx = ks*8 + kcol;         // kk-major: kk*128 + ci
        const int kk   = kidx >> 7;
        const int ci   = kidx & 127;
        c_row = (size_t)l*KPL + (size_t)(half*64 + co_l)*384 + ci*3 + kk;
    } else {
        c_row = gidx;                          // bias rows: KC + l*128 + co
    }

    float acc[BATCH];
    #pragma unroll
    for (int b = 0; b < BATCH; ++b) acc[b] = 0.0f;
    const float4* wr = (const float4*)(w2 + c_row*64);
    #pragma unroll 4
    for (int q = 0; q < 16; ++q) {
        float4 w = wr[q];
        #pragma unroll
        for (int b = 0; b < BATCH; ++b) {
            const float* h = sh + b*64 + q*4;
            acc[b] += w.x*h[0] + w.y*h[1] + w.z*h[2] + w.w*h[3];
        }
    }
    const float bias = b2[c_row];
    if (isK) {
        #pragma unroll
        for (int b = 0; b < BATCH; ++b) {
            uint32_t u = to_tf32(acc[b] + bias);
            g_W[(size_t)(((b*N_LAYERS + l)*2 + half))*WHALF + e] = __uint_as_float(u);
        }
    } else {
        const int idx2 = gidx - KC;           // l*128 + co
        #pragma unroll
        for (int b = 0; b < BATCH; ++b)
            g_bias[b*N_LAYERS*CH + idx2] = acc[b] + bias;
    }
}

// =========================================================================
// Conv layer via mma.sync tf32. CTA: co-half (64) x full t loop.
// 256 threads = 8 warps: wr=wid&1 -> co 32, wc=wid>>1 -> t 32.
// Warp tile 32co x 32t = 2 m-tiles x 4 n-tiles, k-loop 48 steps of 8.
// x tile kept exact fp32 (residual!); B frags tf32-converted inline.
// =========================================================================
#define SMEM_CONV ((WHALF + CH*XSTRIDE + 128) * 4)

template<int DIL, bool FINAL>
__global__ void __launch_bounds__(256, 1)
lvc_conv_mma(const float* __restrict__ xin, float* __restrict__ xout,
             int layer, const float* __restrict__ alpha) {
    extern __shared__ __align__(16) float smem[];
    float* sW  = smem;                    // WHALF floats (tf32 bits)
    float* sX  = smem + WHALF;            // 128 x XSTRIDE
    float* sB  = sX + CH*XSTRIDE;         // 64
    float* sAl = sB + 64;                 // 64

    const int b    = blockIdx.z;
    const int half = blockIdx.y;
    const int tid  = threadIdx.x;
    const int wid  = tid >> 5;
    const int lane = tid & 31;
    const int wr   = wid & 1;             // co 32-half within 64
    const int wc   = wid >> 1;            // t 32-chunk (0..3)

    // stage W: pure linear float4 copy (fragment-major already)
    {
        const float4* Wg = (const float4*)(g_W + (size_t)((b*N_LAYERS + layer)*2 + half)*WHALF);
        float4* sW4 = (float4*)sW;
        #pragma unroll 4
        for (int i = tid; i < WHALF/4; i += 256) sW4[i] = Wg[i];
    }
    if (tid < 64)  sB[tid] = g_bias[(b*N_LAYERS + layer)*CH + half*64 + tid];
    if (FINAL && tid >= 64 && tid < 128) sAl[tid - 64] = alpha[half*64 + tid - 64];

    const float* xb = xin  + (size_t)b*CH*T_AUDIO;
    float*       yb = xout + (size_t)b*CH*T_AUDIO;
    const int width = NT + 2*DIL;
    const uint32_t* sWu = (const uint32_t*)sW;

    for (int tile = blockIdx.x; tile < TILES; tile += CTAS_X) {
        const int t0 = tile * NT;
        __syncthreads();   // previous tile's sX fully consumed
        for (int idx = tid; idx < CH*width; idx += 256) {
            int ci  = idx / width;
            int col = idx - ci*width;
            int t   = t0 - DIL + col;
            sX[ci*XSTRIDE + col] = (t >= 0 && t < T_AUDIO) ? xb[(size_t)ci*T_AUDIO + t] : 0.0f;
        }
        __syncthreads();

        float acc[2][4][4];
        #pragma unroll
        for (int mt = 0; mt < 2; ++mt)
            #pragma unroll
            for (int n = 0; n < 4; ++n)
                #pragma unroll
                for (int q = 0; q < 4; ++q) acc[mt][n][q] = 0.0f;

        #pragma unroll 2
        for (int ks = 0; ks < NSTEP; ++ks) {
            const int kk  = ks >> 4;                  // tap 0..2
            const int ci0 = (ks & 15)*8 + (lane & 3); // ci rows for b0
            const float* xrow = sX + ci0*XSTRIDE + wc*32 + (lane >> 2) + kk*DIL;

            uint32_t a[2][4];
            #pragma unroll
            for (int mt = 0; mt < 2; ++mt) {
                const uint4 av = *(const uint4*)(sWu + ((ks*4 + wr*2 + mt)*32 + lane)*4);
                a[mt][0] = av.x; a[mt][1] = av.y; a[mt][2] = av.z; a[mt][3] = av.w;
            }
            #pragma unroll
            for (int n = 0; n < 4; ++n) {
                uint32_t bf[2];
                bf[0] = to_tf32(xrow[n*8]);
                bf[1] = to_tf32(xrow[n*8 + 4*XSTRIDE]);
                MMA8(acc[0][n], a[0], bf);
                MMA8(acc[1][n], a[1], bf);
            }
        }

        // epilogue: bias + residual (+ snake), write float2 pairs
        #pragma unroll
        for (int mt = 0; mt < 2; ++mt) {
            const int r0 = wr*32 + mt*16 + (lane >> 2);     // co_local (row group 0)
            #pragma unroll
            for (int n = 0; n < 4; ++n) {
                const int c0 = wc*32 + n*8 + (lane & 3)*2;  // t local (even)
                #pragma unroll
                for (int h = 0; h < 2; ++h) {
                    const int co_l = r0 + h*8;
                    const int cog  = half*64 + co_l;
                    const float bias = sB[co_l];
                    float y0 = acc[mt][n][h*2+0] + bias + sX[cog*XSTRIDE + DIL + c0];
                    float y1 = acc[mt][n][h*2+1] + bias + sX[cog*XSTRIDE + DIL + c0 + 1];
                    if (FINAL) {
                        const float a = sAl[co_l];
                        const float inva = 1.0f/(a + 1e-8f);
                        float s0 = sinf(a*y0), s1 = sinf(a*y1);
                        y0 += inva*s0*s0;
                        y1 += inva*s1*s1;
                    }
                    float2 v; v.x = y0; v.y = y1;
                    *(float2*)&yb[(size_t)cog*T_AUDIO + t0 + c0] = v;
                }
            }
        }
    }
}

// =========================================================================
extern "C" void kernel_launch(void* const* d_in, const int* in_sizes, int n_in,
                              void* d_out, int out_size) {
    const float* x     = (const float*)d_in[0];
    const float* cond  = (const float*)d_in[1];
    const float* w0    = (const float*)d_in[2];
    const float* b0    = (const float*)d_in[3];
    const float* w1    = (const float*)d_in[4];
    const float* b1    = (const float*)d_in[5];
    const float* w2    = (const float*)d_in[6];
    const float* b2    = (const float*)d_in[7];
    const float* alpha = (const float*)d_in[8];
    float* out = (float*)d_out;

    float *buf0, *buf1;
    cudaGetSymbolAddress((void**)&buf0, g_buf0);
    cudaGetSymbolAddress((void**)&buf1, g_buf1);

    const int smemA = (COND_CH*T_MEL + 64*COND_CH*5 + 64*64*3 + 64*T_MEL + 64*T_MEL)
                      * (int)sizeof(float);
    cudaFuncSetAttribute(condnet_kernel, cudaFuncAttributeMaxDynamicSharedMemorySize, smemA);
    condnet_kernel<<<BATCH, 256, smemA>>>(cond, w0, b0, w1, b1);

    weights_kernel<<<(KC + BC)/256, 256>>>(w2, b2);

    cudaFuncSetAttribute(lvc_conv_mma<1,false>, cudaFuncAttributeMaxDynamicSharedMemorySize, SMEM_CONV);
    cudaFuncSetAttribute(lvc_conv_mma<2,false>, cudaFuncAttributeMaxDynamicSharedMemorySize, SMEM_CONV);
    cudaFuncSetAttribute(lvc_conv_mma<4,false>, cudaFuncAttributeMaxDynamicSharedMemorySize, SMEM_CONV);
    cudaFuncSetAttribute(lvc_conv_mma<8,true >, cudaFuncAttributeMaxDynamicSharedMemorySize, SMEM_CONV);

    dim3 grid(CTAS_X, 2, BATCH);
    lvc_conv_mma<1,false><<<grid, 256, SMEM_CONV>>>(x,    buf0, 0, nullptr);
    lvc_conv_mma<2,false><<<grid, 256, SMEM_CONV>>>(buf0, buf1, 1, nullptr);
    lvc_conv_mma<4,false><<<grid, 256, SMEM_CONV>>>(buf1, buf0, 2, nullptr);
    lvc_conv_mma<8,true ><<<grid, 256, SMEM_CONV>>>(buf0, out,  3, alpha);
}

// round 5
// speedup vs baseline: 2.5498x; 1.2861x over previous
#include <cuda_runtime.h>
#include <math.h>
#include <stdint.h>

#define BATCH    8
#define CH       128
#define T_AUDIO  16384
#define COND_CH  80
#define T_MEL    32
#define N_LAYERS 4
#define KPL      (CH*CH*3)        /* 49152 */
#define KC       (KPL*N_LAYERS)   /* 196608 */
#define BC       (CH*N_LAYERS)    /* 512 */

#define KTOT     384
#define NSTEP    48               /* 384/8 k-steps */
#define NT       128              /* t-tile */
#define TILES    (T_AUDIO/NT)     /* 128 */
#define CTAS_X   9                /* persistent groups per (b,half) */
#define WHALF    24576            /* 64co x 384k floats per (b,l,half) */
#define XSTRIDE  152              /* x tile row stride: 152%32=24 -> B frags conflict-free */

// ---------------- device scratch ----------------
__device__ float g_hmean[BATCH*64];
__device__ float g_W[BATCH*N_LAYERS*2*WHALF];      // fragment-major per (b,l,half)
__device__ float g_bias[BATCH*N_LAYERS*CH];
__device__ float g_buf0[(size_t)BATCH*CH*T_AUDIO];
__device__ float g_buf1[(size_t)BATCH*CH*T_AUDIO];

__device__ __forceinline__ float gelu_exact(float x) {
    return 0.5f * x * (1.0f + erff(x * 0.7071067811865475f));
}
__device__ __forceinline__ uint32_t to_tf32(float f) {
    uint32_t u;
    asm("cvt.rna.tf32.f32 %0, %1;" : "=r"(u) : "f"(f));
    return u;
}

#define MMA8(d_, a_, b_) \
  asm volatile("mma.sync.aligned.m16n8k8.row.col.f32.tf32.tf32.f32 " \
    "{%0,%1,%2,%3}, {%4,%5,%6,%7}, {%8,%9}, {%0,%1,%2,%3};" \
    : "+f"((d_)[0]), "+f"((d_)[1]), "+f"((d_)[2]), "+f"((d_)[3]) \
    : "r"((a_)[0]), "r"((a_)[1]), "r"((a_)[2]), "r"((a_)[3]), \
      "r"((b_)[0]), "r"((b_)[1]))

// =========================================================================
// Kernel A: conditioning net (unchanged)
// =========================================================================
__global__ void condnet_kernel(const float* __restrict__ cond,
                               const float* __restrict__ w0, const float* __restrict__ b0,
                               const float* __restrict__ w1, const float* __restrict__ b1) {
    extern __shared__ float smemf[];
    float* sc  = smemf;
    float* sw0 = sc  + COND_CH*T_MEL;
    float* sw1 = sw0 + 64*COND_CH*5;
    float* sh0 = sw1 + 64*64*3;
    float* sh1 = sh0 + 64*T_MEL;

    const int b = blockIdx.x;
    const int tid = threadIdx.x;

    for (int i = tid; i < COND_CH*T_MEL; i += 256) sc[i]  = cond[b*COND_CH*T_MEL + i];
    for (int i = tid; i < 64*COND_CH*5;  i += 256) sw0[i] = w0[i];
    for (int i = tid; i < 64*64*3;       i += 256) sw1[i] = w1[i];
    __syncthreads();

    const int og = tid >> 5;
    const int t  = tid & 31;

    float acc[8];
    #pragma unroll
    for (int r = 0; r < 8; ++r) acc[r] = b0[og*8 + r];
    for (int i = 0; i < COND_CH; ++i) {
        #pragma unroll
        for (int k = 0; k < 5; ++k) {
            int tt = t + k - 2;
            if (tt >= 0 && tt < T_MEL) {
                float xv = sc[i*T_MEL + tt];
                #pragma unroll
                for (int r = 0; r < 8; ++r)
                    acc[r] += sw0[((og*8 + r)*COND_CH + i)*5 + k] * xv;
            }
        }
    }
    #pragma unroll
    for (int r = 0; r < 8; ++r) sh0[(og*8 + r)*T_MEL + t] = gelu_exact(acc[r]);
    __syncthreads();

    #pragma unroll
    for (int r = 0; r < 8; ++r) acc[r] = b1[og*8 + r];
    for (int i = 0; i < 64; ++i) {
        #pragma unroll
        for (int k = 0; k < 3; ++k) {
            int tt = t + k - 1;
            if (tt >= 0 && tt < T_MEL) {
                float xv = sh0[i*T_MEL + tt];
                #pragma unroll
                for (int r = 0; r < 8; ++r)
                    acc[r] += sw1[((og*8 + r)*64 + i)*3 + k] * xv;
            }
        }
    }
    #pragma unroll
    for (int r = 0; r < 8; ++r) sh1[(og*8 + r)*T_MEL + t] = gelu_exact(acc[r]);
    __syncthreads();

    if (tid < 64) {
        float s = 0.0f;
        #pragma unroll
        for (int tt = 0; tt < T_MEL; ++tt) s += sh1[tid*T_MEL + tt];
        g_hmean[b*64 + tid] = s * (1.0f/T_MEL);
    }
}

// =========================================================================
// Kernel B: LVC weights -> mma-fragment-major, tf32-pre-rounded (unchanged)
// =========================================================================
__global__ void weights_kernel(const float* __restrict__ w2,
                               const float* __restrict__ b2) {
    __shared__ float sh[BATCH*64];
    const int tid = threadIdx.x;
    for (int i = tid; i < BATCH*64; i += 256) sh[i] = g_hmean[i];
    __syncthreads();

    const int gidx = blockIdx.x*256 + tid;    // < 197120
    size_t c_row;
    int l = 0, half = 0, e = 0;
    const bool isK = gidx < KC;
    if (isK) {
        l = gidx / (2*WHALF);
        int rem = gidx - l*(2*WHALF);
        half = rem / WHALF;
        e = rem - half*WHALF;
        const int j    = e & 3;
        const int lane = (e >> 2) & 31;
        const int mt   = (e >> 7) & 3;
        const int ks   = e >> 9;
        const int co_l = mt*16 + (lane >> 2) + (j & 1)*8;
        const int kcol = (lane & 3) + ((j >> 1) & 1)*4;
        const int kidx = ks*8 + kcol;         // kk-major: kk*128 + ci
        const int kk   = kidx >> 7;
        const int ci   = kidx & 127;
        c_row = (size_t)l*KPL + (size_t)(half*64 + co_l)*384 + ci*3 + kk;
    } else {
        c_row = gidx;                          // bias rows: KC + l*128 + co
    }

    float acc[BATCH];
    #pragma unroll
    for (int b = 0; b < BATCH; ++b) acc[b] = 0.0f;
    const float4* wr = (const float4*)(w2 + c_row*64);
    #pragma unroll 4
    for (int q = 0; q < 16; ++q) {
        float4 w = wr[q];
        #pragma unroll
        for (int b = 0; b < BATCH; ++b) {
            const float* h = sh + b*64 + q*4;
            acc[b] += w.x*h[0] + w.y*h[1] + w.z*h[2] + w.w*h[3];
        }
    }
    const float bias = b2[c_row];
    if (isK) {
        #pragma unroll
        for (int b = 0; b < BATCH; ++b) {
            uint32_t u = to_tf32(acc[b] + bias);
            g_W[(size_t)(((b*N_LAYERS + l)*2 + half))*WHALF + e] = __uint_as_float(u);
        }
    } else {
        const int idx2 = gidx - KC;           // l*128 + co
        #pragma unroll
        for (int b = 0; b < BATCH; ++b)
            g_bias[b*N_LAYERS*CH + idx2] = acc[b] + bias;
    }
}

// =========================================================================
// Conv via mma.sync tf32. 512 threads = 16 warps.
// Warp (wr = wid&1, wc = wid>>1): 32co x 16t tile = 2 m-tiles x 2 n-tiles.
// x staged into smem ALREADY tf32 (one cvt per element); residual re-read
// from gmem at the epilogue (exact fp32, L2-warm).
// =========================================================================
#define SMEM_CONV ((WHALF + CH*XSTRIDE + 128) * 4)

template<int DIL, bool FINAL>
__global__ void __launch_bounds__(512, 1)
lvc_conv_mma(const float* __restrict__ xin, float* __restrict__ xout,
             int layer, const float* __restrict__ alpha) {
    extern __shared__ __align__(16) float smem[];
    float* sW  = smem;                    // WHALF floats (tf32 bits)
    float* sX  = smem + WHALF;            // 128 x XSTRIDE (tf32 bits)
    float* sB  = sX + CH*XSTRIDE;         // 64
    float* sAl = sB + 64;                 // 64

    const int b    = blockIdx.z;
    const int half = blockIdx.y;
    const int tid  = threadIdx.x;
    const int wid  = tid >> 5;
    const int lane = tid & 31;
    const int wr   = wid & 1;             // co 32-half within 64
    const int wc   = wid >> 1;            // t 16-chunk (0..7)

    // stage W: pure linear float4 copy (fragment-major already)
    {
        const float4* Wg = (const float4*)(g_W + (size_t)((b*N_LAYERS + layer)*2 + half)*WHALF);
        float4* sW4 = (float4*)sW;
        #pragma unroll 4
        for (int i = tid; i < WHALF/4; i += 512) sW4[i] = Wg[i];
    }
    if (tid < 64)  sB[tid] = g_bias[(b*N_LAYERS + layer)*CH + half*64 + tid];
    if (FINAL && tid >= 64 && tid < 128) sAl[tid - 64] = alpha[half*64 + tid - 64];

    const float* xb = xin  + (size_t)b*CH*T_AUDIO;
    float*       yb = xout + (size_t)b*CH*T_AUDIO;
    const int width = NT + 2*DIL;
    const uint32_t* sWu = (const uint32_t*)sW;
    const uint32_t* sXu = (const uint32_t*)sX;

    for (int tile = blockIdx.x; tile < TILES; tile += CTAS_X) {
        const int t0 = tile * NT;
        __syncthreads();   // previous tile's sX fully consumed
        for (int idx = tid; idx < CH*width; idx += 512) {
            int ci  = idx / width;
            int col = idx - ci*width;
            int t   = t0 - DIL + col;
            float v = (t >= 0 && t < T_AUDIO) ? xb[(size_t)ci*T_AUDIO + t] : 0.0f;
            ((uint32_t*)sX)[ci*XSTRIDE + col] = to_tf32(v);
        }
        __syncthreads();

        float acc[2][2][4];
        #pragma unroll
        for (int mt = 0; mt < 2; ++mt)
            #pragma unroll
            for (int n = 0; n < 2; ++n)
                #pragma unroll
                for (int q = 0; q < 4; ++q) acc[mt][n][q] = 0.0f;

        #pragma unroll 4
        for (int ks = 0; ks < NSTEP; ++ks) {
            const int kk  = ks >> 4;                  // tap 0..2
            const int ci0 = (ks & 15)*8 + (lane & 3); // ci rows for b0
            const uint32_t* xrow = sXu + ci0*XSTRIDE + wc*16 + (lane >> 2) + kk*DIL;

            uint32_t a[2][4];
            #pragma unroll
            for (int mt = 0; mt < 2; ++mt) {
                const uint4 av = *(const uint4*)(sWu + ((ks*4 + wr*2 + mt)*32 + lane)*4);
                a[mt][0] = av.x; a[mt][1] = av.y; a[mt][2] = av.z; a[mt][3] = av.w;
            }
            #pragma unroll
            for (int n = 0; n < 2; ++n) {
                uint32_t bf[2];
                bf[0] = xrow[n*8];
                bf[1] = xrow[n*8 + 4*XSTRIDE];
                MMA8(acc[0][n], a[0], bf);
                MMA8(acc[1][n], a[1], bf);
            }
        }

        // epilogue: bias + residual (from gmem, exact) (+ snake)
        #pragma unroll
        for (int mt = 0; mt < 2; ++mt) {
            const int r0 = wr*32 + mt*16 + (lane >> 2);     // co_local base
            #pragma unroll
            for (int n = 0; n < 2; ++n) {
                const int c0 = wc*16 + n*8 + (lane & 3)*2;  // t local (even)
                #pragma unroll
                for (int h = 0; h < 2; ++h) {
                    const int co_l = r0 + h*8;
                    const int cog  = half*64 + co_l;
                    const float bias = sB[co_l];
                    const float2 xres = *(const float2*)&xb[(size_t)cog*T_AUDIO + t0 + c0];
                    float y0 = acc[mt][n][h*2+0] + bias + xres.x;
                    float y1 = acc[mt][n][h*2+1] + bias + xres.y;
                    if (FINAL) {
                        const float a = sAl[co_l];
                        const float inva = 1.0f/(a + 1e-8f);
                        float s0 = sinf(a*y0), s1 = sinf(a*y1);
                        y0 += inva*s0*s0;
                        y1 += inva*s1*s1;
                    }
                    float2 v; v.x = y0; v.y = y1;
                    *(float2*)&yb[(size_t)cog*T_AUDIO + t0 + c0] = v;
                }
            }
        }
    }
}

// =========================================================================
extern "C" void kernel_launch(void* const* d_in, const int* in_sizes, int n_in,
                              void* d_out, int out_size) {
    const float* x     = (const float*)d_in[0];
    const float* cond  = (const float*)d_in[1];
    const float* w0    = (const float*)d_in[2];
    const float* b0    = (const float*)d_in[3];
    const float* w1    = (const float*)d_in[4];
    const float* b1    = (const float*)d_in[5];
    const float* w2    = (const float*)d_in[6];
    const float* b2    = (const float*)d_in[7];
    const float* alpha = (const float*)d_in[8];
    float* out = (float*)d_out;

    float *buf0, *buf1;
    cudaGetSymbolAddress((void**)&buf0, g_buf0);
    cudaGetSymbolAddress((void**)&buf1, g_buf1);

    const int smemA = (COND_CH*T_MEL + 64*COND_CH*5 + 64*64*3 + 64*T_MEL + 64*T_MEL)
                      * (int)sizeof(float);
    cudaFuncSetAttribute(condnet_kernel, cudaFuncAttributeMaxDynamicSharedMemorySize, smemA);
    condnet_kernel<<<BATCH, 256, smemA>>>(cond, w0, b0, w1, b1);

    weights_kernel<<<(KC + BC)/256, 256>>>(w2, b2);

    cudaFuncSetAttribute(lvc_conv_mma<1,false>, cudaFuncAttributeMaxDynamicSharedMemorySize, SMEM_CONV);
    cudaFuncSetAttribute(lvc_conv_mma<2,false>, cudaFuncAttributeMaxDynamicSharedMemorySize, SMEM_CONV);
    cudaFuncSetAttribute(lvc_conv_mma<4,false>, cudaFuncAttributeMaxDynamicSharedMemorySize, SMEM_CONV);
    cudaFuncSetAttribute(lvc_conv_mma<8,true >, cudaFuncAttributeMaxDynamicSharedMemorySize, SMEM_CONV);

    dim3 grid(CTAS_X, 2, BATCH);
    lvc_conv_mma<1,false><<<grid, 512, SMEM_CONV>>>(x,    buf0, 0, nullptr);
    lvc_conv_mma<2,false><<<grid, 512, SMEM_CONV>>>(buf0, buf1, 1, nullptr);
    lvc_conv_mma<4,false><<<grid, 512, SMEM_CONV>>>(buf1, buf0, 2, nullptr);
    lvc_conv_mma<8,true ><<<grid, 512, SMEM_CONV>>>(buf0, out,  3, alpha);
}

// round 6
// speedup vs baseline: 2.5958x; 1.0181x over previous
#include <cuda_runtime.h>
#include <math.h>
#include <stdint.h>

#define BATCH    8
#define CH       128
#define T_AUDIO  16384
#define COND_CH  80
#define T_MEL    32
#define N_LAYERS 4
#define KPL      (CH*CH*3)        /* 49152 */
#define KC       (KPL*N_LAYERS)   /* 196608 */
#define BC       (CH*N_LAYERS)    /* 512 */

#define KTOT     384
#define KSTEPS   24               /* 384/16 bf16 k-steps */
#define NT       128              /* t-tile */
#define TILES    (T_AUDIO/NT)     /* 128 */
#define CTAS_X   18
#define WHALF2   12288            /* 64co x 384k / 2 packed bf16x2 per (b,l,half) */
#define XR       168              /* x-pair tile row stride (words); 168%32==8 -> B frags conflict-free */

// ---------------- device scratch ----------------
__device__ float    g_hmean[BATCH*64];
__device__ uint32_t g_Wh[BATCH*N_LAYERS*2*WHALF2];   // bf16x2 fragment-major
__device__ float    g_bias[BATCH*N_LAYERS*CH];
__device__ float    g_buf0[(size_t)BATCH*CH*T_AUDIO];
__device__ float    g_buf1[(size_t)BATCH*CH*T_AUDIO];

__device__ __forceinline__ float gelu_exact(float x) {
    return 0.5f * x * (1.0f + erff(x * 0.7071067811865475f));
}
__device__ __forceinline__ uint32_t pack_bf16x2(float lo, float hi) {
    uint32_t u;
    asm("cvt.rn.bf16x2.f32 %0, %1, %2;" : "=r"(u) : "f"(hi), "f"(lo));
    return u;
}

#define MMA16(d_, a_, b_) \
  asm volatile("mma.sync.aligned.m16n8k16.row.col.f32.bf16.bf16.f32 " \
    "{%0,%1,%2,%3}, {%4,%5,%6,%7}, {%8,%9}, {%0,%1,%2,%3};" \
    : "+f"((d_)[0]), "+f"((d_)[1]), "+f"((d_)[2]), "+f"((d_)[3]) \
    : "r"((a_)[0]), "r"((a_)[1]), "r"((a_)[2]), "r"((a_)[3]), \
      "r"((b_)[0]), "r"((b_)[1]))

// =========================================================================
// Kernel A: conditioning net (unchanged)
// =========================================================================
__global__ void condnet_kernel(const float* __restrict__ cond,
                               const float* __restrict__ w0, const float* __restrict__ b0,
                               const float* __restrict__ w1, const float* __restrict__ b1) {
    extern __shared__ float smemf[];
    float* sc  = smemf;
    float* sw0 = sc  + COND_CH*T_MEL;
    float* sw1 = sw0 + 64*COND_CH*5;
    float* sh0 = sw1 + 64*64*3;
    float* sh1 = sh0 + 64*T_MEL;

    const int b = blockIdx.x;
    const int tid = threadIdx.x;

    for (int i = tid; i < COND_CH*T_MEL; i += 256) sc[i]  = cond[b*COND_CH*T_MEL + i];
    for (int i = tid; i < 64*COND_CH*5;  i += 256) sw0[i] = w0[i];
    for (int i = tid; i < 64*64*3;       i += 256) sw1[i] = w1[i];
    __syncthreads();

    const int og = tid >> 5;
    const int t  = tid & 31;

    float acc[8];
    #pragma unroll
    for (int r = 0; r < 8; ++r) acc[r] = b0[og*8 + r];
    for (int i = 0; i < COND_CH; ++i) {
        #pragma unroll
        for (int k = 0; k < 5; ++k) {
            int tt = t + k - 2;
            if (tt >= 0 && tt < T_MEL) {
                float xv = sc[i*T_MEL + tt];
                #pragma unroll
                for (int r = 0; r < 8; ++r)
                    acc[r] += sw0[((og*8 + r)*COND_CH + i)*5 + k] * xv;
            }
        }
    }
    #pragma unroll
    for (int r = 0; r < 8; ++r) sh0[(og*8 + r)*T_MEL + t] = gelu_exact(acc[r]);
    __syncthreads();

    #pragma unroll
    for (int r = 0; r < 8; ++r) acc[r] = b1[og*8 + r];
    for (int i = 0; i < 64; ++i) {
        #pragma unroll
        for (int k = 0; k < 3; ++k) {
            int tt = t + k - 1;
            if (tt >= 0 && tt < T_MEL) {
                float xv = sh0[i*T_MEL + tt];
                #pragma unroll
                for (int r = 0; r < 8; ++r)
                    acc[r] += sw1[((og*8 + r)*64 + i)*3 + k] * xv;
            }
        }
    }
    #pragma unroll
    for (int r = 0; r < 8; ++r) sh1[(og*8 + r)*T_MEL + t] = gelu_exact(acc[r]);
    __syncthreads();

    if (tid < 64) {
        float s = 0.0f;
        #pragma unroll
        for (int tt = 0; tt < T_MEL; ++tt) s += sh1[tid*T_MEL + tt];
        g_hmean[b*64 + tid] = s * (1.0f/T_MEL);
    }
}

// =========================================================================
// Kernel B: LVC weights -> bf16x2-packed m16n8k16 A-fragment-major layout.
// Blocks 0..383: packed W elems (each thread = one bf16x2 = two k_locals,
// for all 8 batches). Blocks 384..385: bias rows (fp32, exact).
// =========================================================================
__global__ void weights_kernel(const float* __restrict__ w2,
                               const float* __restrict__ b2) {
    __shared__ float sh[BATCH*64];
    const int tid = threadIdx.x;
    for (int i = tid; i < BATCH*64; i += 256) sh[i] = g_hmean[i];
    __syncthreads();

    if (blockIdx.x < 384) {
        const int gidx = blockIdx.x*256 + tid;     // < 98304
        const int lh   = gidx / WHALF2;            // 0..7
        const int l    = lh >> 1;
        const int half = lh & 1;
        const int e2   = gidx - lh*WHALF2;
        const int j    = e2 & 3;
        const int lane = (e2 >> 2) & 31;
        const int mt   = (e2 >> 7) & 3;
        const int ks   = e2 >> 9;                  // 0..23
        const int co   = mt*16 + (lane >> 2) + (j & 1)*8;
        const int kl0  = (lane & 3)*2 + ((j >> 1) & 1)*8;   // even
        const int kg0  = ks*16 + kl0;
        const int kk   = kg0 >> 7;                 // tap (same for kg0, kg0+1)
        const int ci0  = kg0 & 127;
        const size_t base = (size_t)l*KPL + (size_t)(half*64 + co)*384 + kk;
        const size_t r0 = base + (size_t)ci0*3;
        const size_t r1 = r0 + 3;                  // ci0+1

        float a0[BATCH], a1[BATCH];
        #pragma unroll
        for (int b = 0; b < BATCH; ++b) { a0[b] = 0.0f; a1[b] = 0.0f; }
        const float4* wr0 = (const float4*)(w2 + r0*64);
        const float4* wr1 = (const float4*)(w2 + r1*64);
        #pragma unroll 4
        for (int q = 0; q < 16; ++q) {
            float4 u = wr0[q], v = wr1[q];
            #pragma unroll
            for (int b = 0; b < BATCH; ++b) {
                const float* h = sh + b*64 + q*4;
                a0[b] += u.x*h[0] + u.y*h[1] + u.z*h[2] + u.w*h[3];
                a1[b] += v.x*h[0] + v.y*h[1] + v.z*h[2] + v.w*h[3];
            }
        }
        const float bi0 = b2[r0], bi1 = b2[r1];
        #pragma unroll
        for (int b = 0; b < BATCH; ++b)
            g_Wh[(size_t)((b*N_LAYERS + l)*2 + half)*WHALF2 + e2] =
                pack_bf16x2(a0[b] + bi0, a1[b] + bi1);
    } else {
        const int idx = (blockIdx.x - 384)*256 + tid;   // < 512
        const size_t c = (size_t)KC + idx;
        float acc[BATCH];
        #pragma unroll
        for (int b = 0; b < BATCH; ++b) acc[b] = 0.0f;
        const float4* wr = (const float4*)(w2 + c*64);
        #pragma unroll 4
        for (int q = 0; q < 16; ++q) {
            float4 w = wr[q];
            #pragma unroll
            for (int b = 0; b < BATCH; ++b) {
                const float* h = sh + b*64 + q*4;
                acc[b] += w.x*h[0] + w.y*h[1] + w.z*h[2] + w.w*h[3];
            }
        }
        const float bias = b2[c];
        #pragma unroll
        for (int b = 0; b < BATCH; ++b)
            g_bias[b*N_LAYERS*CH + idx] = acc[b] + bias;
    }
}

// =========================================================================
// Conv via mma.sync bf16 m16n8k16. 256 threads, 2 CTAs/SM.
// CTA = 64co x 128t tile; 8 warps (wr=wid&1 -> 32co, wc=wid>>1 -> 32t);
// warp = 32co x 32t = 2 m-tiles x 4 n-tiles, 24 k-steps.
// x tile in smem as bf16x2 ci-pairs: sXB[ci>>1][t], row stride XR=168
// (168%32==8 -> B frag lanes hit 32 distinct banks).
// Residual/bias exact fp32 from gmem/smem in epilogue.
// =========================================================================
#define SMEM_CONV ((WHALF2 + 64*XR + 128) * 4)

template<int DIL, bool FINAL>
__global__ void __launch_bounds__(256, 2)
lvc_conv_bf16(const float* __restrict__ xin, float* __restrict__ xout,
              int layer, const float* __restrict__ alpha) {
    extern __shared__ __align__(16) uint32_t smem[];
    uint32_t* sW  = smem;                 // WHALF2 bf16x2
    uint32_t* sXB = smem + WHALF2;        // 64 x XR bf16x2
    float*    sB  = (float*)(smem + WHALF2 + 64*XR);   // 64
    float*    sAl = sB + 64;                            // 64

    const int b    = blockIdx.z;
    const int half = blockIdx.y;
    const int tid  = threadIdx.x;
    const int wid  = tid >> 5;
    const int lane = tid & 31;
    const int wr   = wid & 1;             // co 32-half within 64
    const int wc   = wid >> 1;            // t 32-chunk (0..3)

    // stage W (fragment-major bf16x2): linear uint4 copy
    {
        const uint4* Wg = (const uint4*)(g_Wh + (size_t)((b*N_LAYERS + layer)*2 + half)*WHALF2);
        uint4* sW4 = (uint4*)sW;
        #pragma unroll 4
        for (int i = tid; i < WHALF2/4; i += 256) sW4[i] = Wg[i];
    }
    if (tid < 64)  sB[tid] = g_bias[(b*N_LAYERS + layer)*CH + half*64 + tid];
    if (FINAL && tid >= 64 && tid < 128) sAl[tid - 64] = alpha[half*64 + tid - 64];

    const float* xb = xin  + (size_t)b*CH*T_AUDIO;
    float*       yb = xout + (size_t)b*CH*T_AUDIO;
    const int width = NT + 2*DIL;

    for (int tile = blockIdx.x; tile < TILES; tile += CTAS_X) {
        const int t0 = tile * NT;
        __syncthreads();   // W ready / previous tile fully consumed
        // stage x: 64 pair-rows x width, pack fp32 pair -> bf16x2
        #pragma unroll 1
        for (int idx = tid; idx < 64*width; idx += 256) {
            const int r   = idx / width;
            const int col = idx - r*width;
            const int t   = t0 - DIL + col;
            float lo = 0.0f, hi = 0.0f;
            if (t >= 0 && t < T_AUDIO) {
                lo = xb[(size_t)(2*r)*T_AUDIO + t];
                hi = xb[(size_t)(2*r + 1)*T_AUDIO + t];
            }
            sXB[r*XR + col] = pack_bf16x2(lo, hi);
        }
        __syncthreads();

        float acc[2][4][4];
        #pragma unroll
        for (int mt = 0; mt < 2; ++mt)
            #pragma unroll
            for (int n = 0; n < 4; ++n)
                #pragma unroll
                for (int q = 0; q < 4; ++q) acc[mt][n][q] = 0.0f;

        #pragma unroll 4
        for (int ks = 0; ks < KSTEPS; ++ks) {
            const int kk   = ks >> 3;                    // tap 0..2
            const int row0 = (ks & 7)*8 + (lane & 3);    // ci-pair row for b0
            const uint32_t* xrow = sXB + row0*XR + wc*32 + (lane >> 2) + kk*DIL;

            uint32_t a[2][4];
            #pragma unroll
            for (int mt = 0; mt < 2; ++mt) {
                const uint4 av = *(const uint4*)(sW + ((ks*4 + wr*2 + mt)*32 + lane)*4);
                a[mt][0] = av.x; a[mt][1] = av.y; a[mt][2] = av.z; a[mt][3] = av.w;
            }
            #pragma unroll
            for (int n = 0; n < 4; ++n) {
                uint32_t bf[2];
                bf[0] = xrow[n*8];
                bf[1] = xrow[n*8 + 4*XR];
                MMA16(acc[0][n], a[0], bf);
                MMA16(acc[1][n], a[1], bf);
            }
        }

        // epilogue: bias + residual (gmem, exact fp32) (+ snake)
        #pragma unroll
        for (int mt = 0; mt < 2; ++mt) {
            const int r0 = wr*32 + mt*16 + (lane >> 2);
            #pragma unroll
            for (int n = 0; n < 4; ++n) {
                const int c0 = wc*32 + n*8 + (lane & 3)*2;
                #pragma unroll
                for (int h = 0; h < 2; ++h) {
                    const int co_l = r0 + h*8;
                    const int cog  = half*64 + co_l;
                    const float bias = sB[co_l];
                    const float2 xres = *(const float2*)&xb[(size_t)cog*T_AUDIO + t0 + c0];
                    float y0 = acc[mt][n][h*2+0] + bias + xres.x;
                    float y1 = acc[mt][n][h*2+1] + bias + xres.y;
                    if (FINAL) {
                        const float a = sAl[co_l];
                        const float inva = 1.0f/(a + 1e-8f);
                        float s0 = sinf(a*y0), s1 = sinf(a*y1);
                        y0 += inva*s0*s0;
                        y1 += inva*s1*s1;
                    }
                    float2 v; v.x = y0; v.y = y1;
                    *(float2*)&yb[(size_t)cog*T_AUDIO + t0 + c0] = v;
                }
            }
        }
    }
}

// =========================================================================
extern "C" void kernel_launch(void* const* d_in, const int* in_sizes, int n_in,
                              void* d_out, int out_size) {
    const float* x     = (const float*)d_in[0];
    const float* cond  = (const float*)d_in[1];
    const float* w0    = (const float*)d_in[2];
    const float* b0    = (const float*)d_in[3];
    const float* w1    = (const float*)d_in[4];
    const float* b1    = (const float*)d_in[5];
    const float* w2    = (const float*)d_in[6];
    const float* b2    = (const float*)d_in[7];
    const float* alpha = (const float*)d_in[8];
    float* out = (float*)d_out;

    float *buf0, *buf1;
    cudaGetSymbolAddress((void**)&buf0, g_buf0);
    cudaGetSymbolAddress((void**)&buf1, g_buf1);

    const int smemA = (COND_CH*T_MEL + 64*COND_CH*5 + 64*64*3 + 64*T_MEL + 64*T_MEL)
                      * (int)sizeof(float);
    cudaFuncSetAttribute(condnet_kernel, cudaFuncAttributeMaxDynamicSharedMemorySize, smemA);
    condnet_kernel<<<BATCH, 256, smemA>>>(cond, w0, b0, w1, b1);

    weights_kernel<<<386, 256>>>(w2, b2);

    cudaFuncSetAttribute(lvc_conv_bf16<1,false>, cudaFuncAttributeMaxDynamicSharedMemorySize, SMEM_CONV);
    cudaFuncSetAttribute(lvc_conv_bf16<2,false>, cudaFuncAttributeMaxDynamicSharedMemorySize, SMEM_CONV);
    cudaFuncSetAttribute(lvc_conv_bf16<4,false>, cudaFuncAttributeMaxDynamicSharedMemorySize, SMEM_CONV);
    cudaFuncSetAttribute(lvc_conv_bf16<8,true >, cudaFuncAttributeMaxDynamicSharedMemorySize, SMEM_CONV);

    dim3 grid(CTAS_X, 2, BATCH);
    lvc_conv_bf16<1,false><<<grid, 256, SMEM_CONV>>>(x,    buf0, 0, nullptr);
    lvc_conv_bf16<2,false><<<grid, 256, SMEM_CONV>>>(buf0, buf1, 1, nullptr);
    lvc_conv_bf16<4,false><<<grid, 256, SMEM_CONV>>>(buf1, buf0, 2, nullptr);
    lvc_conv_bf16<8,true ><<<grid, 256, SMEM_CONV>>>(buf0, out,  3, alpha);
}

// round 7
// speedup vs baseline: 4.5960x; 1.7705x over previous
#include <cuda_runtime.h>
#include <math.h>
#include <stdint.h>

#define BATCH    8
#define CH       128
#define T_AUDIO  16384
#define COND_CH  80
#define T_MEL    32
#define N_LAYERS 4
#define KPL      (CH*CH*3)        /* 49152 */
#define KC       (KPL*N_LAYERS)   /* 196608 */
#define BC       (CH*N_LAYERS)    /* 512 */

#define KSTEPS   24               /* 384/16 bf16 k-steps */
#define NT       128              /* t-tile */
#define TILES    (T_AUDIO/NT)     /* 128 */
#define CTAS_X   9
#define WHALF2   12288            /* 96 frag-rows x 32 lanes x 4 words */
#define PAD      16
#define XROW     (T_AUDIO + 2*PAD)  /* 16416 words per packed pair-row */
#define XSTR     152              /* smem x-buffer stride: 152%32==24 -> conflict-free */
#define XCHUNKS  36               /* 144 words = 36 x 16B per row */

// ---------------- device scratch ----------------
__device__ float    g_hmean[BATCH*64];
__device__ uint32_t g_Wh[BATCH*N_LAYERS*2*WHALF2];
__device__ float    g_bias[BATCH*N_LAYERS*CH];
__device__ float    g_buf0[(size_t)BATCH*CH*T_AUDIO];
__device__ float    g_buf1[(size_t)BATCH*CH*T_AUDIO];
__device__ uint32_t g_xbf0[(size_t)BATCH*64*XROW];   // bf16x2 shadow (pads stay zero)
__device__ uint32_t g_xbf1[(size_t)BATCH*64*XROW];

__device__ __forceinline__ float gelu_exact(float x) {
    return 0.5f * x * (1.0f + erff(x * 0.7071067811865475f));
}
__device__ __forceinline__ uint32_t pack_bf16x2(float lo, float hi) {
    uint32_t u;
    asm("cvt.rn.bf16x2.f32 %0, %1, %2;" : "=r"(u) : "f"(hi), "f"(lo));
    return u;
}
__device__ __forceinline__ uint32_t smem_u32(const void* p) {
    uint32_t a;
    asm("{ .reg .u64 t; cvta.to.shared.u64 t, %1; cvt.u32.u64 %0, t; }" : "=r"(a) : "l"(p));
    return a;
}
__device__ __forceinline__ void cp16(uint32_t dst, const void* src) {
    asm volatile("cp.async.cg.shared.global [%0], [%1], 16;" :: "r"(dst), "l"(src));
}
#define CP_COMMIT() asm volatile("cp.async.commit_group;" ::: "memory")
#define CP_WAIT0()  asm volatile("cp.async.wait_group 0;" ::: "memory")

#define MMA16(d_, a_, b_) \
  asm volatile("mma.sync.aligned.m16n8k16.row.col.f32.bf16.bf16.f32 " \
    "{%0,%1,%2,%3}, {%4,%5,%6,%7}, {%8,%9}, {%0,%1,%2,%3};" \
    : "+f"((d_)[0]), "+f"((d_)[1]), "+f"((d_)[2]), "+f"((d_)[3]) \
    : "r"((a_)[0]), "r"((a_)[1]), "r"((a_)[2]), "r"((a_)[3]), \
      "r"((b_)[0]), "r"((b_)[1]))

// =========================================================================
// Kernel A: conditioning net (unchanged)
// =========================================================================
__global__ void condnet_kernel(const float* __restrict__ cond,
                               const float* __restrict__ w0, const float* __restrict__ b0,
                               const float* __restrict__ w1, const float* __restrict__ b1) {
    extern __shared__ float smemf[];
    float* sc  = smemf;
    float* sw0 = sc  + COND_CH*T_MEL;
    float* sw1 = sw0 + 64*COND_CH*5;
    float* sh0 = sw1 + 64*64*3;
    float* sh1 = sh0 + 64*T_MEL;

    const int b = blockIdx.x;
    const int tid = threadIdx.x;

    for (int i = tid; i < COND_CH*T_MEL; i += 256) sc[i]  = cond[b*COND_CH*T_MEL + i];
    for (int i = tid; i < 64*COND_CH*5;  i += 256) sw0[i] = w0[i];
    for (int i = tid; i < 64*64*3;       i += 256) sw1[i] = w1[i];
    __syncthreads();

    const int og = tid >> 5;
    const int t  = tid & 31;

    float acc[8];
    #pragma unroll
    for (int r = 0; r < 8; ++r) acc[r] = b0[og*8 + r];
    for (int i = 0; i < COND_CH; ++i) {
        #pragma unroll
        for (int k = 0; k < 5; ++k) {
            int tt = t + k - 2;
            if (tt >= 0 && tt < T_MEL) {
                float xv = sc[i*T_MEL + tt];
                #pragma unroll
                for (int r = 0; r < 8; ++r)
                    acc[r] += sw0[((og*8 + r)*COND_CH + i)*5 + k] * xv;
            }
        }
    }
    #pragma unroll
    for (int r = 0; r < 8; ++r) sh0[(og*8 + r)*T_MEL + t] = gelu_exact(acc[r]);
    __syncthreads();

    #pragma unroll
    for (int r = 0; r < 8; ++r) acc[r] = b1[og*8 + r];
    for (int i = 0; i < 64; ++i) {
        #pragma unroll
        for (int k = 0; k < 3; ++k) {
            int tt = t + k - 1;
            if (tt >= 0 && tt < T_MEL) {
                float xv = sh0[i*T_MEL + tt];
                #pragma unroll
                for (int r = 0; r < 8; ++r)
                    acc[r] += sw1[((og*8 + r)*64 + i)*3 + k] * xv;
            }
        }
    }
    #pragma unroll
    for (int r = 0; r < 8; ++r) sh1[(og*8 + r)*T_MEL + t] = gelu_exact(acc[r]);
    __syncthreads();

    if (tid < 64) {
        float s = 0.0f;
        #pragma unroll
        for (int tt = 0; tt < T_MEL; ++tt) s += sh1[tid*T_MEL + tt];
        g_hmean[b*64 + tid] = s * (1.0f/T_MEL);
    }
}

// =========================================================================
// Kernel B: LVC weights -> bf16x2 fragment-major (unchanged from R6)
// =========================================================================
__global__ void weights_kernel(const float* __restrict__ w2,
                               const float* __restrict__ b2) {
    __shared__ float sh[BATCH*64];
    const int tid = threadIdx.x;
    for (int i = tid; i < BATCH*64; i += 256) sh[i] = g_hmean[i];
    __syncthreads();

    if (blockIdx.x < 384) {
        const int gidx = blockIdx.x*256 + tid;     // < 98304
        const int lh   = gidx / WHALF2;
        const int l    = lh >> 1;
        const int half = lh & 1;
        const int e2   = gidx - lh*WHALF2;
        const int j    = e2 & 3;
        const int lane = (e2 >> 2) & 31;
        const int mt   = (e2 >> 7) & 3;
        const int ks   = e2 >> 9;
        const int co   = mt*16 + (lane >> 2) + (j & 1)*8;
        const int kl0  = (lane & 3)*2 + ((j >> 1) & 1)*8;
        const int kg0  = ks*16 + kl0;
        const int kk   = kg0 >> 7;
        const int ci0  = kg0 & 127;
        const size_t base = (size_t)l*KPL + (size_t)(half*64 + co)*384 + kk;
        const size_t r0 = base + (size_t)ci0*3;
        const size_t r1 = r0 + 3;

        float a0[BATCH], a1[BATCH];
        #pragma unroll
        for (int b = 0; b < BATCH; ++b) { a0[b] = 0.0f; a1[b] = 0.0f; }
        const float4* wr0 = (const float4*)(w2 + r0*64);
        const float4* wr1 = (const float4*)(w2 + r1*64);
        #pragma unroll 4
        for (int q = 0; q < 16; ++q) {
            float4 u = wr0[q], v = wr1[q];
            #pragma unroll
            for (int b = 0; b < BATCH; ++b) {
                const float* h = sh + b*64 + q*4;
                a0[b] += u.x*h[0] + u.y*h[1] + u.z*h[2] + u.w*h[3];
                a1[b] += v.x*h[0] + v.y*h[1] + v.z*h[2] + v.w*h[3];
            }
        }
        const float bi0 = b2[r0], bi1 = b2[r1];
        #pragma unroll
        for (int b = 0; b < BATCH; ++b)
            g_Wh[(size_t)((b*N_LAYERS + l)*2 + half)*WHALF2 + e2] =
                pack_bf16x2(a0[b] + bi0, a1[b] + bi1);
    } else {
        const int idx = (blockIdx.x - 384)*256 + tid;
        const size_t c = (size_t)KC + idx;
        float acc[BATCH];
        #pragma unroll
        for (int b = 0; b < BATCH; ++b) acc[b] = 0.0f;
        const float4* wr = (const float4*)(w2 + c*64);
        #pragma unroll 4
        for (int q = 0; q < 16; ++q) {
            float4 w = wr[q];
            #pragma unroll
            for (int b = 0; b < BATCH; ++b) {
                const float* h = sh + b*64 + q*4;
                acc[b] += w.x*h[0] + w.y*h[1] + w.z*h[2] + w.w*h[3];
            }
        }
        const float bias = b2[c];
        #pragma unroll
        for (int b = 0; b < BATCH; ++b)
            g_bias[b*N_LAYERS*CH + idx] = acc[b] + bias;
    }
}

// =========================================================================
// Kernel C: pack input x -> bf16x2 shadow (pair-interleaved, padded rows)
// =========================================================================
__global__ void pack_x_kernel(const float* __restrict__ x) {
    const int b = blockIdx.z;
    const int p = blockIdx.y;
    const int t = (blockIdx.x*256 + threadIdx.x)*4;
    const float4 a = *(const float4*)&x[((size_t)(b*CH + 2*p))*T_AUDIO + t];
    const float4 c = *(const float4*)&x[((size_t)(b*CH + 2*p + 1))*T_AUDIO + t];
    uint4 o;
    o.x = pack_bf16x2(a.x, c.x);
    o.y = pack_bf16x2(a.y, c.y);
    o.z = pack_bf16x2(a.z, c.z);
    o.w = pack_bf16x2(a.w, c.w);
    *(uint4*)&g_xbf0[(size_t)(b*64 + p)*XROW + PAD + t] = o;
}

// =========================================================================
// Conv via bf16 mma + cp.async double-buffered staging.
// 512 threads, 1 CTA/SM. CTA = (b, half=64co), strided tiles of 128 t.
// Warp (wr=wid&1 -> 32 co, wc=wid>>1 -> 16 t): 2 m-tiles x 2 n-tiles.
// Epilogue: exact fp32 residual from gmem; writes fp32 y and (non-final)
// bf16x2 shadow via shfl-pairing.
// =========================================================================
#define SMEM_CONV ((WHALF2 + 2*64*XSTR + 128) * 4)

template<int DIL, bool FINAL>
__global__ void __launch_bounds__(512, 1)
lvc_conv_bf16(const uint32_t* __restrict__ xbf_in, uint32_t* __restrict__ xbf_out,
              const float* __restrict__ xres, float* __restrict__ yout,
              int layer, const float* __restrict__ alpha) {
    extern __shared__ __align__(16) uint32_t smem[];
    uint32_t* sW  = smem;                       // 12288
    uint32_t* sX[2] = { smem + WHALF2, smem + WHALF2 + 64*XSTR };
    float*    sB  = (float*)(smem + WHALF2 + 2*64*XSTR);
    float*    sAl = sB + 64;

    const int b    = blockIdx.z;
    const int half = blockIdx.y;
    const int tid  = threadIdx.x;
    const int wid  = tid >> 5;
    const int lane = tid & 31;
    const int wr   = wid & 1;
    const int wc   = wid >> 1;                  // 0..7 (16 t each)

    // stage W via cp.async (overlapped with first x tile)
    {
        const uint32_t dW = smem_u32(sW);
        const uint32_t* Wg = g_Wh + (size_t)((b*N_LAYERS + layer)*2 + half)*WHALF2;
        #pragma unroll
        for (int i = tid; i < WHALF2/4; i += 512)
            cp16(dW + i*16, Wg + i*4);
    }
    if (tid < 64)  sB[tid] = g_bias[(b*N_LAYERS + layer)*CH + half*64 + tid];
    if (FINAL && tid >= 64 && tid < 128) sAl[tid - 64] = alpha[half*64 + tid - 64];

    const uint32_t* xin_b = xbf_in + (size_t)b*64*XROW;
    const uint32_t dX[2] = { smem_u32(sX[0]), smem_u32(sX[1]) };

    // stage first tile
    int tile = blockIdx.x;
    {
        const int t0 = tile * NT;
        #pragma unroll
        for (int idx = tid; idx < 64*XCHUNKS; idx += 512) {
            const int row = idx / XCHUNKS;
            const int ch  = idx - row*XCHUNKS;
            cp16(dX[0] + (row*XSTR + ch*4)*4,
                 xin_b + (size_t)row*XROW + (PAD - 8 + t0) + ch*4);
        }
        CP_COMMIT();
    }

    const float* xr_b = xres + (size_t)b*CH*T_AUDIO;
    float*       yo_b = yout + (size_t)b*CH*T_AUDIO;
    uint32_t*    xo_b = FINAL ? nullptr : (xbf_out + (size_t)b*64*XROW);

    int bufi = 0;
    for (; tile < TILES; tile += CTAS_X) {
        const int t0 = tile * NT;
        CP_WAIT0();
        __syncthreads();      // tile data + W visible; prev MMA done everywhere

        const int nxt = tile + CTAS_X;
        if (nxt < TILES) {
            const int nt0 = nxt * NT;
            #pragma unroll
            for (int idx = tid; idx < 64*XCHUNKS; idx += 512) {
                const int row = idx / XCHUNKS;
                const int ch  = idx - row*XCHUNKS;
                cp16(dX[bufi^1] + (row*XSTR + ch*4)*4,
                     xin_b + (size_t)row*XROW + (PAD - 8 + nt0) + ch*4);
            }
            CP_COMMIT();
        }

        const uint32_t* sXb = sX[bufi];
        float acc[2][2][4];
        #pragma unroll
        for (int mt = 0; mt < 2; ++mt)
            #pragma unroll
            for (int n = 0; n < 2; ++n)
                #pragma unroll
                for (int q = 0; q < 4; ++q) acc[mt][n][q] = 0.0f;

        #pragma unroll 4
        for (int ks = 0; ks < KSTEPS; ++ks) {
            const int kk   = ks >> 3;                  // tap 0..2
            const int row0 = (ks & 7)*8 + (lane & 3);
            const uint32_t* xrow = sXb + row0*XSTR + wc*16 + (lane >> 2)
                                   + 8 + (kk - 1)*DIL;
            uint32_t a[2][4];
            #pragma unroll
            for (int mt = 0; mt < 2; ++mt) {
                const uint4 av = *(const uint4*)(sW + ((ks*4 + wr*2 + mt)*32 + lane)*4);
                a[mt][0] = av.x; a[mt][1] = av.y; a[mt][2] = av.z; a[mt][3] = av.w;
            }
            #pragma unroll
            for (int n = 0; n < 2; ++n) {
                uint32_t bf[2];
                bf[0] = xrow[n*8];
                bf[1] = xrow[n*8 + 4*XSTR];
                MMA16(acc[0][n], a[0], bf);
                MMA16(acc[1][n], a[1], bf);
            }
        }

        // epilogue
        #pragma unroll
        for (int mt = 0; mt < 2; ++mt) {
            #pragma unroll
            for (int n = 0; n < 2; ++n) {
                const int c0 = wc*16 + n*8 + (lane & 3)*2;
                #pragma unroll
                for (int h = 0; h < 2; ++h) {
                    const int co_l = wr*32 + mt*16 + (lane >> 2) + h*8;
                    const int cog  = half*64 + co_l;
                    const float bias = sB[co_l];
                    const float2 xv = *(const float2*)&xr_b[(size_t)cog*T_AUDIO + t0 + c0];
                    float y0 = acc[mt][n][h*2+0] + bias + xv.x;
                    float y1 = acc[mt][n][h*2+1] + bias + xv.y;
                    if (FINAL) {
                        const float a = sAl[co_l];
                        const float inva = 1.0f/(a + 1e-8f);
                        float s0 = sinf(a*y0), s1 = sinf(a*y1);
                        y0 += inva*s0*s0;
                        y1 += inva*s1*s1;
                    }
                    float2 v; v.x = y0; v.y = y1;
                    *(float2*)&yo_b[(size_t)cog*T_AUDIO + t0 + c0] = v;
                    if (!FINAL) {
                        // pair even/odd co across lanes (lane ^ 4) -> bf16x2 shadow
                        const float o0 = __shfl_xor_sync(0xffffffffu, y0, 4);
                        const float o1 = __shfl_xor_sync(0xffffffffu, y1, 4);
                        if ((lane & 4) == 0) {
                            uint2 w;
                            w.x = pack_bf16x2(y0, o0);
                            w.y = pack_bf16x2(y1, o1);
                            const int prow = cog >> 1;
                            *(uint2*)&xo_b[(size_t)prow*XROW + PAD + t0 + c0] = w;
                        }
                    }
                }
            }
        }
        bufi ^= 1;
    }
}

// =========================================================================
extern "C" void kernel_launch(void* const* d_in, const int* in_sizes, int n_in,
                              void* d_out, int out_size) {
    const float* x     = (const float*)d_in[0];
    const float* cond  = (const float*)d_in[1];
    const float* w0    = (const float*)d_in[2];
    const float* b0    = (const float*)d_in[3];
    const float* w1    = (const float*)d_in[4];
    const float* b1    = (const float*)d_in[5];
    const float* w2    = (const float*)d_in[6];
    const float* b2    = (const float*)d_in[7];
    const float* alpha = (const float*)d_in[8];
    float* out = (float*)d_out;

    float *buf0, *buf1;
    uint32_t *xbf0, *xbf1;
    cudaGetSymbolAddress((void**)&buf0, g_buf0);
    cudaGetSymbolAddress((void**)&buf1, g_buf1);
    cudaGetSymbolAddress((void**)&xbf0, g_xbf0);
    cudaGetSymbolAddress((void**)&xbf1, g_xbf1);

    const int smemA = (COND_CH*T_MEL + 64*COND_CH*5 + 64*64*3 + 64*T_MEL + 64*T_MEL)
                      * (int)sizeof(float);
    cudaFuncSetAttribute(condnet_kernel, cudaFuncAttributeMaxDynamicSharedMemorySize, smemA);
    condnet_kernel<<<BATCH, 256, smemA>>>(cond, w0, b0, w1, b1);

    weights_kernel<<<386, 256>>>(w2, b2);
    pack_x_kernel<<<dim3(T_AUDIO/1024, 64, BATCH), 256>>>(x);

    cudaFuncSetAttribute(lvc_conv_bf16<1,false>, cudaFuncAttributeMaxDynamicSharedMemorySize, SMEM_CONV);
    cudaFuncSetAttribute(lvc_conv_bf16<2,false>, cudaFuncAttributeMaxDynamicSharedMemorySize, SMEM_CONV);
    cudaFuncSetAttribute(lvc_conv_bf16<4,false>, cudaFuncAttributeMaxDynamicSharedMemorySize, SMEM_CONV);
    cudaFuncSetAttribute(lvc_conv_bf16<8,true >, cudaFuncAttributeMaxDynamicSharedMemorySize, SMEM_CONV);

    dim3 grid(CTAS_X, 2, BATCH);
    lvc_conv_bf16<1,false><<<grid, 512, SMEM_CONV>>>(xbf0, xbf1, x,    buf0, 0, nullptr);
    lvc_conv_bf16<2,false><<<grid, 512, SMEM_CONV>>>(xbf1, xbf0, buf0, buf1, 1, nullptr);
    lvc_conv_bf16<4,false><<<grid, 512, SMEM_CONV>>>(xbf0, xbf1, buf1, buf0, 2, nullptr);
    lvc_conv_bf16<8,true ><<<grid, 512, SMEM_CONV>>>(xbf1, nullptr, buf0, out, 3, alpha);
}

// round 8
// speedup vs baseline: 4.6790x; 1.0181x over previous
#include <cuda_runtime.h>
#include <math.h>
#include <stdint.h>

#define BATCH    8
#define CH       128
#define T_AUDIO  16384
#define COND_CH  80
#define T_MEL    32
#define N_LAYERS 4
#define KPL      (CH*CH*3)        /* 49152 */
#define KC       (KPL*N_LAYERS)   /* 196608 */
#define BC       (CH*N_LAYERS)    /* 512 */

#define KSTEPS   24               /* 384/16 bf16 k-steps */
#define NT       128              /* t-tile */
#define TILES    (T_AUDIO/NT)     /* 128 */
#define CTAS_X   18
#define WHALF2   12288            /* per (b,l,half): 96 frag-rows x 32 lanes x 4 words */
#define PAD      16
#define XROW     (T_AUDIO + 2*PAD)  /* 16416 words per packed pair-row */
#define XSTR     152              /* smem x stride: 152%32==24 -> B frags conflict-free */
#define XCHUNKS  36               /* 144 words = 36 x 16B per row */
#define PACK_BLKS 8192            /* pack part of prep kernel */

// ---------------- device scratch ----------------
__device__ float    g_hmean[BATCH*64];
__device__ uint32_t g_Wh[BATCH*N_LAYERS*2*WHALF2];
__device__ float    g_bias[BATCH*N_LAYERS*CH];
__device__ float    g_buf0[(size_t)BATCH*CH*T_AUDIO];
__device__ float    g_buf1[(size_t)BATCH*CH*T_AUDIO];
__device__ uint32_t g_xbf0[(size_t)BATCH*64*XROW];   // bf16x2 shadow (pads stay zero)
__device__ uint32_t g_xbf1[(size_t)BATCH*64*XROW];

__device__ __forceinline__ float gelu_exact(float x) {
    return 0.5f * x * (1.0f + erff(x * 0.7071067811865475f));
}
__device__ __forceinline__ uint32_t pack_bf16x2(float lo, float hi) {
    uint32_t u;
    asm("cvt.rn.bf16x2.f32 %0, %1, %2;" : "=r"(u) : "f"(hi), "f"(lo));
    return u;
}
__device__ __forceinline__ uint32_t smem_u32(const void* p) {
    uint32_t a;
    asm("{ .reg .u64 t; cvta.to.shared.u64 t, %1; cvt.u32.u64 %0, t; }" : "=r"(a) : "l"(p));
    return a;
}
__device__ __forceinline__ void cp16(uint32_t dst, const void* src) {
    asm volatile("cp.async.cg.shared.global [%0], [%1], 16;" :: "r"(dst), "l"(src));
}
#define CP_COMMIT() asm volatile("cp.async.commit_group;" ::: "memory")
#define CP_WAIT0()  asm volatile("cp.async.wait_group 0;" ::: "memory")

#define MMA16(d_, a_, b_) \
  asm volatile("mma.sync.aligned.m16n8k16.row.col.f32.bf16.bf16.f32 " \
    "{%0,%1,%2,%3}, {%4,%5,%6,%7}, {%8,%9}, {%0,%1,%2,%3};" \
    : "+f"((d_)[0]), "+f"((d_)[1]), "+f"((d_)[2]), "+f"((d_)[3]) \
    : "r"((a_)[0]), "r"((a_)[1]), "r"((a_)[2]), "r"((a_)[3]), \
      "r"((b_)[0]), "r"((b_)[1]))

// =========================================================================
// Kernel A: conditioning net (unchanged)
// =========================================================================
__global__ void condnet_kernel(const float* __restrict__ cond,
                               const float* __restrict__ w0, const float* __restrict__ b0,
                               const float* __restrict__ w1, const float* __restrict__ b1) {
    extern __shared__ float smemf[];
    float* sc  = smemf;
    float* sw0 = sc  + COND_CH*T_MEL;
    float* sw1 = sw0 + 64*COND_CH*5;
    float* sh0 = sw1 + 64*64*3;
    float* sh1 = sh0 + 64*T_MEL;

    const int b = blockIdx.x;
    const int tid = threadIdx.x;

    for (int i = tid; i < COND_CH*T_MEL; i += 256) sc[i]  = cond[b*COND_CH*T_MEL + i];
    for (int i = tid; i < 64*COND_CH*5;  i += 256) sw0[i] = w0[i];
    for (int i = tid; i < 64*64*3;       i += 256) sw1[i] = w1[i];
    __syncthreads();

    const int og = tid >> 5;
    const int t  = tid & 31;

    float acc[8];
    #pragma unroll
    for (int r = 0; r < 8; ++r) acc[r] = b0[og*8 + r];
    for (int i = 0; i < COND_CH; ++i) {
        #pragma unroll
        for (int k = 0; k < 5; ++k) {
            int tt = t + k - 2;
            if (tt >= 0 && tt < T_MEL) {
                float xv = sc[i*T_MEL + tt];
                #pragma unroll
                for (int r = 0; r < 8; ++r)
                    acc[r] += sw0[((og*8 + r)*COND_CH + i)*5 + k] * xv;
            }
        }
    }
    #pragma unroll
    for (int r = 0; r < 8; ++r) sh0[(og*8 + r)*T_MEL + t] = gelu_exact(acc[r]);
    __syncthreads();

    #pragma unroll
    for (int r = 0; r < 8; ++r) acc[r] = b1[og*8 + r];
    for (int i = 0; i < 64; ++i) {
        #pragma unroll
        for (int k = 0; k < 3; ++k) {
            int tt = t + k - 1;
            if (tt >= 0 && tt < T_MEL) {
                float xv = sh0[i*T_MEL + tt];
                #pragma unroll
                for (int r = 0; r < 8; ++r)
                    acc[r] += sw1[((og*8 + r)*64 + i)*3 + k] * xv;
            }
        }
    }
    #pragma unroll
    for (int r = 0; r < 8; ++r) sh1[(og*8 + r)*T_MEL + t] = gelu_exact(acc[r]);
    __syncthreads();

    if (tid < 64) {
        float s = 0.0f;
        #pragma unroll
        for (int tt = 0; tt < T_MEL; ++tt) s += sh1[tid*T_MEL + tt];
        g_hmean[b*64 + tid] = s * (1.0f/T_MEL);
    }
}

// =========================================================================
// Kernel B (prep): blocks 0..385 = LVC weights -> bf16x2 fragment-major;
// blocks 386.. = pack input x -> bf16x2 shadow. Fused to overlap the two
// independent memory streams in one launch.
// =========================================================================
__global__ void prep_kernel(const float* __restrict__ w2,
                            const float* __restrict__ b2,
                            const float* __restrict__ x) {
    const int tid = threadIdx.x;

    if (blockIdx.x >= 386) {
        // ---- pack x ----
        const int i = blockIdx.x - 386;          // < 8192
        const int tc = i & 15;                   // t chunk (1024 t each)
        const int p  = (i >> 4) & 63;            // pair row
        const int b  = i >> 10;                  // batch
        const int t  = (tc*256 + tid)*4;
        const float4 a = *(const float4*)&x[((size_t)(b*CH + 2*p))*T_AUDIO + t];
        const float4 c = *(const float4*)&x[((size_t)(b*CH + 2*p + 1))*T_AUDIO + t];
        uint4 o;
        o.x = pack_bf16x2(a.x, c.x);
        o.y = pack_bf16x2(a.y, c.y);
        o.z = pack_bf16x2(a.z, c.z);
        o.w = pack_bf16x2(a.w, c.w);
        *(uint4*)&g_xbf0[(size_t)(b*64 + p)*XROW + PAD + t] = o;
        return;
    }

    __shared__ float sh[BATCH*64];
    for (int i = tid; i < BATCH*64; i += 256) sh[i] = g_hmean[i];
    __syncthreads();

    if (blockIdx.x < 384) {
        const int gidx = blockIdx.x*256 + tid;     // < 98304
        const int lh   = gidx / WHALF2;
        const int l    = lh >> 1;
        const int half = lh & 1;
        const int e2   = gidx - lh*WHALF2;
        const int j    = e2 & 3;
        const int lane = (e2 >> 2) & 31;
        const int mt   = (e2 >> 7) & 3;
        const int ks   = e2 >> 9;
        const int co   = mt*16 + (lane >> 2) + (j & 1)*8;
        const int kl0  = (lane & 3)*2 + ((j >> 1) & 1)*8;
        const int kg0  = ks*16 + kl0;
        const int kk   = kg0 >> 7;
        const int ci0  = kg0 & 127;
        const size_t base = (size_t)l*KPL + (size_t)(half*64 + co)*384 + kk;
        const size_t r0 = base + (size_t)ci0*3;
        const size_t r1 = r0 + 3;

        float a0[BATCH], a1[BATCH];
        #pragma unroll
        for (int b = 0; b < BATCH; ++b) { a0[b] = 0.0f; a1[b] = 0.0f; }
        const float4* wr0 = (const float4*)(w2 + r0*64);
        const float4* wr1 = (const float4*)(w2 + r1*64);
        #pragma unroll 4
        for (int q = 0; q < 16; ++q) {
            float4 u = wr0[q], v = wr1[q];
            #pragma unroll
            for (int b = 0; b < BATCH; ++b) {
                const float* h = sh + b*64 + q*4;
                a0[b] += u.x*h[0] + u.y*h[1] + u.z*h[2] + u.w*h[3];
                a1[b] += v.x*h[0] + v.y*h[1] + v.z*h[2] + v.w*h[3];
            }
        }
        const float bi0 = b2[r0], bi1 = b2[r1];
        #pragma unroll
        for (int b = 0; b < BATCH; ++b)
            g_Wh[(size_t)((b*N_LAYERS + l)*2 + half)*WHALF2 + e2] =
                pack_bf16x2(a0[b] + bi0, a1[b] + bi1);
    } else {
        const int idx = (blockIdx.x - 384)*256 + tid;   // < 512
        const size_t c = (size_t)KC + idx;
        float acc[BATCH];
        #pragma unroll
        for (int b = 0; b < BATCH; ++b) acc[b] = 0.0f;
        const float4* wr = (const float4*)(w2 + c*64);
        #pragma unroll 4
        for (int q = 0; q < 16; ++q) {
            float4 w = wr[q];
            #pragma unroll
            for (int b = 0; b < BATCH; ++b) {
                const float* h = sh + b*64 + q*4;
                acc[b] += w.x*h[0] + w.y*h[1] + w.z*h[2] + w.w*h[3];
            }
        }
        const float bias = b2[c];
        #pragma unroll
        for (int b = 0; b < BATCH; ++b)
            g_bias[b*N_LAYERS*CH + idx] = acc[b] + bias;
    }
}

// =========================================================================
// Conv via bf16 mma + cp.async double buffering. FULL-CH CTA:
// 512 threads, 1 CTA/SM; CTA = (b), 128 co x 128 t tiles, strided.
// 16 warps: wr = wid&3 -> 32co group; wc = wid>>2 -> 32t group.
// Warp tile 32co x 32t = 2 m-tiles x 4 n-tiles (2 wf per HMMA).
// W smem holds both halves: [half][frag]. x tile staged ONCE per CTA.
// =========================================================================
#define SMEM_CONV ((2*WHALF2 + 2*64*XSTR + 256) * 4)

template<int DIL, bool FINAL>
__global__ void __launch_bounds__(512, 1)
lvc_conv_bf16(const uint32_t* __restrict__ xbf_in, uint32_t* __restrict__ xbf_out,
              const float* __restrict__ xres, float* __restrict__ yout,
              int layer, const float* __restrict__ alpha) {
    extern __shared__ __align__(16) uint32_t smem[];
    uint32_t* sW  = smem;                       // 2*WHALF2
    uint32_t* sX[2] = { smem + 2*WHALF2, smem + 2*WHALF2 + 64*XSTR };
    float*    sB  = (float*)(smem + 2*WHALF2 + 2*64*XSTR);   // 128
    float*    sAl = sB + 128;                                 // 128

    const int b    = blockIdx.y;
    const int tid  = threadIdx.x;
    const int wid  = tid >> 5;
    const int lane = tid & 31;
    const int wr   = wid & 3;                   // co group (32 co)
    const int wc   = wid >> 2;                  // t group (32 t)

    // stage W (both halves) via cp.async
    {
        const uint32_t dW = smem_u32(sW);
        const uint32_t* Wg = g_Wh + (size_t)(b*N_LAYERS + layer)*2*WHALF2;
        #pragma unroll
        for (int i = tid; i < 2*WHALF2/4; i += 512)
            cp16(dW + i*16, Wg + i*4);
    }
    if (tid < 128) sB[tid] = g_bias[(b*N_LAYERS + layer)*CH + tid];
    if (FINAL && tid >= 128 && tid < 256) sAl[tid - 128] = alpha[tid - 128];

    const uint32_t* xin_b = xbf_in + (size_t)b*64*XROW;
    const uint32_t dX[2] = { smem_u32(sX[0]), smem_u32(sX[1]) };

    // stage first tile
    int tile = blockIdx.x;
    {
        const int t0 = tile * NT;
        #pragma unroll
        for (int idx = tid; idx < 64*XCHUNKS; idx += 512) {
            const int row = idx / XCHUNKS;
            const int ch  = idx - row*XCHUNKS;
            cp16(dX[0] + (row*XSTR + ch*4)*4,
                 xin_b + (size_t)row*XROW + (PAD - 8 + t0) + ch*4);
        }
        CP_COMMIT();
    }

    const float* xr_b = xres + (size_t)b*CH*T_AUDIO;
    float*       yo_b = yout + (size_t)b*CH*T_AUDIO;
    uint32_t*    xo_b = FINAL ? nullptr : (xbf_out + (size_t)b*64*XROW);

    int bufi = 0;
    for (; tile < TILES; tile += CTAS_X) {
        const int t0 = tile * NT;
        CP_WAIT0();
        __syncthreads();

        const int nxt = tile + CTAS_X;
        if (nxt < TILES) {
            const int nt0 = nxt * NT;
            #pragma unroll
            for (int idx = tid; idx < 64*XCHUNKS; idx += 512) {
                const int row = idx / XCHUNKS;
                const int ch  = idx - row*XCHUNKS;
                cp16(dX[bufi^1] + (row*XSTR + ch*4)*4,
                     xin_b + (size_t)row*XROW + (PAD - 8 + nt0) + ch*4);
            }
            CP_COMMIT();
        }

        const uint32_t* sXb = sX[bufi];
        float acc[2][4][4];
        #pragma unroll
        for (int mt = 0; mt < 2; ++mt)
            #pragma unroll
            for (int n = 0; n < 4; ++n)
                #pragma unroll
                for (int q = 0; q < 4; ++q) acc[mt][n][q] = 0.0f;

        const int half = wr >> 1;                 // which 64-co half
        const uint32_t* sWh = sW + half*WHALF2;

        #pragma unroll 1
        for (int kk = 0; kk < 3; ++kk) {
            #pragma unroll
            for (int ks8 = 0; ks8 < 8; ++ks8) {
                const int ks   = kk*8 + ks8;
                const int row0 = ks8*8 + (lane & 3);
                const uint32_t* xrow = sXb + row0*XSTR + wc*32 + (lane >> 2)
                                       + 8 + (kk - 1)*DIL;
                uint32_t a[2][4];
                #pragma unroll
                for (int mt = 0; mt < 2; ++mt) {
                    const uint4 av = *(const uint4*)(sWh + ((ks*4 + (wr&1)*2 + mt)*32 + lane)*4);
                    a[mt][0] = av.x; a[mt][1] = av.y; a[mt][2] = av.z; a[mt][3] = av.w;
                }
                #pragma unroll
                for (int n = 0; n < 4; ++n) {
                    uint32_t bf[2];
                    bf[0] = xrow[n*8];
                    bf[1] = xrow[n*8 + 4*XSTR];
                    MMA16(acc[0][n], a[0], bf);
                    MMA16(acc[1][n], a[1], bf);
                }
            }
        }

        // epilogue
        #pragma unroll
        for (int mt = 0; mt < 2; ++mt) {
            #pragma unroll
            for (int n = 0; n < 4; ++n) {
                const int c0 = wc*32 + n*8 + (lane & 3)*2;
                #pragma unroll
                for (int h = 0; h < 2; ++h) {
                    const int cog = wr*32 + mt*16 + (lane >> 2) + h*8;
                    const float bias = sB[cog];
                    const float2 xv = *(const float2*)&xr_b[(size_t)cog*T_AUDIO + t0 + c0];
                    float y0 = acc[mt][n][h*2+0] + bias + xv.x;
                    float y1 = acc[mt][n][h*2+1] + bias + xv.y;
                    if (FINAL) {
                        const float a = sAl[cog];
                        const float inva = 1.0f/(a + 1e-8f);
                        float s0 = sinf(a*y0), s1 = sinf(a*y1);
                        y0 += inva*s0*s0;
                        y1 += inva*s1*s1;
                    }
                    float2 v; v.x = y0; v.y = y1;
                    *(float2*)&yo_b[(size_t)cog*T_AUDIO + t0 + c0] = v;
                    if (!FINAL) {
                        const float o0 = __shfl_xor_sync(0xffffffffu, y0, 4);
                        const float o1 = __shfl_xor_sync(0xffffffffu, y1, 4);
                        if ((lane & 4) == 0) {
                            uint2 w;
                            w.x = pack_bf16x2(y0, o0);
                            w.y = pack_bf16x2(y1, o1);
                            const int prow = cog >> 1;
                            *(uint2*)&xo_b[(size_t)prow*XROW + PAD + t0 + c0] = w;
                        }
                    }
                }
            }
        }
        bufi ^= 1;
    }
}

// =========================================================================
extern "C" void kernel_launch(void* const* d_in, const int* in_sizes, int n_in,
                              void* d_out, int out_size) {
    const float* x     = (const float*)d_in[0];
    const float* cond  = (const float*)d_in[1];
    const float* w0    = (const float*)d_in[2];
    const float* b0    = (const float*)d_in[3];
    const float* w1    = (const float*)d_in[4];
    const float* b1    = (const float*)d_in[5];
    const float* w2    = (const float*)d_in[6];
    const float* b2    = (const float*)d_in[7];
    const float* alpha = (const float*)d_in[8];
    float* out = (float*)d_out;

    float *buf0, *buf1;
    uint32_t *xbf0, *xbf1;
    cudaGetSymbolAddress((void**)&buf0, g_buf0);
    cudaGetSymbolAddress((void**)&buf1, g_buf1);
    cudaGetSymbolAddress((void**)&xbf0, g_xbf0);
    cudaGetSymbolAddress((void**)&xbf1, g_xbf1);

    const int smemA = (COND_CH*T_MEL + 64*COND_CH*5 + 64*64*3 + 64*T_MEL + 64*T_MEL)
                      * (int)sizeof(float);
    cudaFuncSetAttribute(condnet_kernel, cudaFuncAttributeMaxDynamicSharedMemorySize, smemA);
    condnet_kernel<<<BATCH, 256, smemA>>>(cond, w0, b0, w1, b1);

    prep_kernel<<<386 + PACK_BLKS, 256>>>(w2, b2, x);

    cudaFuncSetAttribute(lvc_conv_bf16<1,false>, cudaFuncAttributeMaxDynamicSharedMemorySize, SMEM_CONV);
    cudaFuncSetAttribute(lvc_conv_bf16<2,false>, cudaFuncAttributeMaxDynamicSharedMemorySize, SMEM_CONV);
    cudaFuncSetAttribute(lvc_conv_bf16<4,false>, cudaFuncAttributeMaxDynamicSharedMemorySize, SMEM_CONV);
    cudaFuncSetAttribute(lvc_conv_bf16<8,true >, cudaFuncAttributeMaxDynamicSharedMemorySize, SMEM_CONV);

    dim3 grid(CTAS_X, BATCH);
    lvc_conv_bf16<1,false><<<grid, 512, SMEM_CONV>>>(xbf0, xbf1, x,    buf0, 0, nullptr);
    lvc_conv_bf16<2,false><<<grid, 512, SMEM_CONV>>>(xbf1, xbf0, buf0, buf1, 1, nullptr);
    lvc_conv_bf16<4,false><<<grid, 512, SMEM_CONV>>>(xbf0, xbf1, buf1, buf0, 2, nullptr);
    lvc_conv_bf16<8,true ><<<grid, 512, SMEM_CONV>>>(xbf1, nullptr, buf0, out, 3, alpha);
}